// round 1
// baseline (speedup 1.0000x reference)
#include <cuda_runtime.h>
#include <math.h>

#define S_  1024
#define B_  4
#define H_  768
#define NH_ 12
#define HD_ 64
#define FF_ 3072
#define E_  4
#define T_  4096
#define H3_ 2304

// ---------------- scratch (static __device__, no allocation) ----------------
__device__ float g_ln1[(size_t)T_ * H_];
__device__ float g_qkv[(size_t)T_ * H3_];
__device__ float g_ctx[(size_t)T_ * H_];
__device__ float g_x1 [(size_t)T_ * H_];
__device__ float g_ln2[(size_t)T_ * H_];
__device__ float g_h1 [(size_t)T_ * FF_];
__device__ int   g_eidx[T_];
__device__ float g_prob[T_];
__device__ int   g_perm[T_];
__device__ int   g_cnt [E_];
__device__ int   g_off [E_ + 1];
__device__ int   g_fill[E_];

// ---------------- layernorm ----------------
__device__ __forceinline__ void ln_row(const float* __restrict__ x, float* __restrict__ y,
                                       const float* __restrict__ w, const float* __restrict__ b) {
    __shared__ float red[2][8];
    int tid = threadIdx.x;                // 256 threads, 3 elems each (H=768)
    float v0 = x[tid], v1 = x[tid + 256], v2 = x[tid + 512];
    float s  = v0 + v1 + v2;
    float ss = v0 * v0 + v1 * v1 + v2 * v2;
    for (int o = 16; o; o >>= 1) {
        s  += __shfl_xor_sync(0xffffffffu, s,  o);
        ss += __shfl_xor_sync(0xffffffffu, ss, o);
    }
    if ((tid & 31) == 0) { red[0][tid >> 5] = s; red[1][tid >> 5] = ss; }
    __syncthreads();
    if (tid < 32) {
        float a = (tid < 8) ? red[0][tid] : 0.f;
        float c = (tid < 8) ? red[1][tid] : 0.f;
        for (int o = 4; o; o >>= 1) {
            a += __shfl_xor_sync(0xffffffffu, a, o);
            c += __shfl_xor_sync(0xffffffffu, c, o);
        }
        if (tid == 0) { red[0][0] = a; red[1][0] = c; }
    }
    __syncthreads();
    float mean = red[0][0] * (1.0f / H_);
    float var  = red[1][0] * (1.0f / H_) - mean * mean;
    float inv  = rsqrtf(var + 1e-5f);
    y[tid]       = (v0 - mean) * inv * w[tid]       + b[tid];
    y[tid + 256] = (v1 - mean) * inv * w[tid + 256] + b[tid + 256];
    y[tid + 512] = (v2 - mean) * inv * w[tid + 512] + b[tid + 512];
}

__global__ void k_ln1(const float* __restrict__ hidden,
                      const float* __restrict__ w, const float* __restrict__ b) {
    ln_row(hidden + (size_t)blockIdx.x * H_, g_ln1 + (size_t)blockIdx.x * H_, w, b);
}
__global__ void k_ln2(const float* __restrict__ w, const float* __restrict__ b) {
    ln_row(g_x1 + (size_t)blockIdx.x * H_, g_ln2 + (size_t)blockIdx.x * H_, w, b);
}

// ---------------- QKV GEMM: C[T,2304] = ln1[T,768] * W[2304,768]^T + bias ----------------
__global__ void k_qkv(const float* __restrict__ W, const float* __restrict__ bias) {
    __shared__ float As[16][65], Bs[16][65];
    int n0 = blockIdx.x * 64, m0 = blockIdx.y * 64;
    int tx = threadIdx.x, ty = threadIdx.y, tid = ty * 16 + tx;
    int lr = tid >> 2, lk = (tid & 3) * 4;
    float acc[4][4] = {};
    const float* Arow = g_ln1 + (size_t)(m0 + lr) * H_ + lk;
    const float* Brow = W     + (size_t)(n0 + lr) * H_ + lk;
    for (int k0 = 0; k0 < H_; k0 += 16) {
        float4 av = *(const float4*)(Arow + k0);
        float4 bv = *(const float4*)(Brow + k0);
        As[lk + 0][lr] = av.x; As[lk + 1][lr] = av.y; As[lk + 2][lr] = av.z; As[lk + 3][lr] = av.w;
        Bs[lk + 0][lr] = bv.x; Bs[lk + 1][lr] = bv.y; Bs[lk + 2][lr] = bv.z; Bs[lk + 3][lr] = bv.w;
        __syncthreads();
#pragma unroll
        for (int kk = 0; kk < 16; kk++) {
            float a[4], b4[4];
#pragma unroll
            for (int i = 0; i < 4; i++) a[i]  = As[kk][ty * 4 + i];
#pragma unroll
            for (int j = 0; j < 4; j++) b4[j] = Bs[kk][tx * 4 + j];
#pragma unroll
            for (int i = 0; i < 4; i++)
#pragma unroll
                for (int j = 0; j < 4; j++) acc[i][j] = fmaf(a[i], b4[j], acc[i][j]);
        }
        __syncthreads();
    }
#pragma unroll
    for (int i = 0; i < 4; i++) {
        int r = m0 + ty * 4 + i;
#pragma unroll
        for (int j = 0; j < 4; j++) {
            int c = n0 + tx * 4 + j;
            g_qkv[(size_t)r * H3_ + c] = acc[i][j] + bias[c];
        }
    }
}

// ---------------- causal flash attention ----------------
// grid (16 qtiles, NH, B), block (16,16). dyn smem: Qs 64*64 | KP 64*65 | Vs 64*64
__global__ void k_attn() {
    extern __shared__ float sm[];
    float* Qs = sm;                  // 4096
    float* KP = sm + 4096;           // 4160 (K tile, then reused as P tile)
    float* Vs = sm + 4096 + 4160;    // 4096
    int qt = blockIdx.x, n = blockIdx.y, b = blockIdx.z;
    int tx = threadIdx.x, ty = threadIdx.y, tid = ty * 16 + tx;
    int q0 = qt * 64;
    const float SCALE = 0.125f;      // 1/sqrt(64)
    {
        int r = tid >> 4, d4 = (tid & 15) * 4;
        for (int rr = r; rr < 64; rr += 16) {
            float4 v = *(const float4*)(g_qkv + ((size_t)(q0 + rr) * B_ + b) * H3_ + n * 192 + d4);
            float* dst = Qs + rr * 64 + d4;
            dst[0] = v.x * SCALE; dst[1] = v.y * SCALE; dst[2] = v.z * SCALE; dst[3] = v.w * SCALE;
        }
    }
    float o[4][4] = {};
    float m_run[4] = {-1e30f, -1e30f, -1e30f, -1e30f};
    float l_run[4] = {0.f, 0.f, 0.f, 0.f};

    for (int j = 0; j <= qt; ++j) {
        __syncthreads();   // prior O-update done with KP/Vs; Q load visible
        int k0 = j * 64;
        {
            int r = tid >> 4, d4 = (tid & 15) * 4;
            for (int rr = r; rr < 64; rr += 16) {
                const float* base = g_qkv + ((size_t)(k0 + rr) * B_ + b) * H3_ + n * 192;
                float4 kv = *(const float4*)(base + 64 + d4);
                KP[rr * 65 + d4 + 0] = kv.x; KP[rr * 65 + d4 + 1] = kv.y;
                KP[rr * 65 + d4 + 2] = kv.z; KP[rr * 65 + d4 + 3] = kv.w;
                float4 vv = *(const float4*)(base + 128 + d4);
                *(float4*)(Vs + rr * 64 + d4) = vv;
            }
        }
        __syncthreads();
        float sacc[4][4] = {};
#pragma unroll 8
        for (int d = 0; d < 64; ++d) {
            float a[4], kr[4];
#pragma unroll
            for (int i = 0; i < 4; i++) a[i]  = Qs[(ty * 4 + i) * 64 + d];
#pragma unroll
            for (int c = 0; c < 4; c++) kr[c] = KP[(tx * 4 + c) * 65 + d];
#pragma unroll
            for (int i = 0; i < 4; i++)
#pragma unroll
                for (int c = 0; c < 4; c++) sacc[i][c] = fmaf(a[i], kr[c], sacc[i][c]);
        }
        if (j == qt) {
#pragma unroll
            for (int i = 0; i < 4; i++)
#pragma unroll
                for (int c = 0; c < 4; c++)
                    if (tx * 4 + c > ty * 4 + i) sacc[i][c] = -1e30f;
        }
        float mx[4], mnew[4], scl[4], rs[4];
#pragma unroll
        for (int i = 0; i < 4; i++) {
            mx[i] = fmaxf(fmaxf(sacc[i][0], sacc[i][1]), fmaxf(sacc[i][2], sacc[i][3]));
            for (int oo = 8; oo; oo >>= 1)
                mx[i] = fmaxf(mx[i], __shfl_xor_sync(0xffffffffu, mx[i], oo));
            mnew[i] = fmaxf(m_run[i], mx[i]);
            scl[i]  = expf(m_run[i] - mnew[i]);
            m_run[i] = mnew[i];
            rs[i] = 0.f;
#pragma unroll
            for (int c = 0; c < 4; c++) {
                sacc[i][c] = expf(sacc[i][c] - mnew[i]);
                rs[i] += sacc[i][c];
            }
            for (int oo = 8; oo; oo >>= 1)
                rs[i] += __shfl_xor_sync(0xffffffffu, rs[i], oo);
            l_run[i] = l_run[i] * scl[i] + rs[i];
#pragma unroll
            for (int c = 0; c < 4; c++) o[i][c] *= scl[i];
        }
        __syncthreads();  // all K reads done; safe to overwrite with P
#pragma unroll
        for (int i = 0; i < 4; i++)
#pragma unroll
            for (int c = 0; c < 4; c++)
                KP[(ty * 4 + i) * 65 + tx * 4 + c] = sacc[i][c];
        __syncthreads();
#pragma unroll 8
        for (int d = 0; d < 64; ++d) {
            float pi[4], vj[4];
#pragma unroll
            for (int i = 0; i < 4; i++) pi[i] = KP[(ty * 4 + i) * 65 + d];
#pragma unroll
            for (int c = 0; c < 4; c++) vj[c] = Vs[d * 64 + tx * 4 + c];
#pragma unroll
            for (int i = 0; i < 4; i++)
#pragma unroll
                for (int c = 0; c < 4; c++) o[i][c] = fmaf(pi[i], vj[c], o[i][c]);
        }
    }
#pragma unroll
    for (int i = 0; i < 4; i++) {
        float invl = 1.0f / l_run[i];
#pragma unroll
        for (int c = 0; c < 4; c++)
            g_ctx[((size_t)(q0 + ty * 4 + i) * B_ + b) * H_ + n * HD_ + tx * 4 + c] = o[i][c] * invl;
    }
}

// ---------------- dense proj + residual: x1 = hidden + ctx*W^T + b ----------------
__global__ void k_dense(const float* __restrict__ W, const float* __restrict__ bias,
                        const float* __restrict__ hidden) {
    __shared__ float As[16][65], Bs[16][65];
    int n0 = blockIdx.x * 64, m0 = blockIdx.y * 64;
    int tx = threadIdx.x, ty = threadIdx.y, tid = ty * 16 + tx;
    int lr = tid >> 2, lk = (tid & 3) * 4;
    float acc[4][4] = {};
    const float* Arow = g_ctx + (size_t)(m0 + lr) * H_ + lk;
    const float* Brow = W     + (size_t)(n0 + lr) * H_ + lk;
    for (int k0 = 0; k0 < H_; k0 += 16) {
        float4 av = *(const float4*)(Arow + k0);
        float4 bv = *(const float4*)(Brow + k0);
        As[lk + 0][lr] = av.x; As[lk + 1][lr] = av.y; As[lk + 2][lr] = av.z; As[lk + 3][lr] = av.w;
        Bs[lk + 0][lr] = bv.x; Bs[lk + 1][lr] = bv.y; Bs[lk + 2][lr] = bv.z; Bs[lk + 3][lr] = bv.w;
        __syncthreads();
#pragma unroll
        for (int kk = 0; kk < 16; kk++) {
            float a[4], b4[4];
#pragma unroll
            for (int i = 0; i < 4; i++) a[i]  = As[kk][ty * 4 + i];
#pragma unroll
            for (int j = 0; j < 4; j++) b4[j] = Bs[kk][tx * 4 + j];
#pragma unroll
            for (int i = 0; i < 4; i++)
#pragma unroll
                for (int j = 0; j < 4; j++) acc[i][j] = fmaf(a[i], b4[j], acc[i][j]);
        }
        __syncthreads();
    }
#pragma unroll
    for (int i = 0; i < 4; i++) {
        int r = m0 + ty * 4 + i;
#pragma unroll
        for (int j = 0; j < 4; j++) {
            int c = n0 + tx * 4 + j;
            g_x1[(size_t)r * H_ + c] = hidden[(size_t)r * H_ + c] + acc[i][j] + bias[c];
        }
    }
}

// ---------------- gate: softmax over 4 experts, top-1 ----------------
__global__ void k_gate(const float* __restrict__ gw) {
    int gidx = blockIdx.x * blockDim.x + threadIdx.x;
    int t = gidx >> 5, lane = gidx & 31;
    if (t >= T_) return;
    const float* x = g_ln2 + (size_t)t * H_;
    float s0 = 0, s1 = 0, s2 = 0, s3 = 0;
    for (int h = lane; h < H_; h += 32) {
        float xv = x[h];
        s0 = fmaf(xv, gw[h],           s0);
        s1 = fmaf(xv, gw[H_ + h],      s1);
        s2 = fmaf(xv, gw[2 * H_ + h],  s2);
        s3 = fmaf(xv, gw[3 * H_ + h],  s3);
    }
    for (int o = 16; o; o >>= 1) {
        s0 += __shfl_xor_sync(0xffffffffu, s0, o);
        s1 += __shfl_xor_sync(0xffffffffu, s1, o);
        s2 += __shfl_xor_sync(0xffffffffu, s2, o);
        s3 += __shfl_xor_sync(0xffffffffu, s3, o);
    }
    if (lane == 0) {
        float l[4] = {s0, s1, s2, s3};
        float mx = fmaxf(fmaxf(l[0], l[1]), fmaxf(l[2], l[3]));
        float ex[4], z = 0.f;
        for (int e = 0; e < 4; e++) { ex[e] = expf(l[e] - mx); z += ex[e]; }
        int best = 0; float bp = ex[0];
        for (int e = 1; e < 4; e++) if (ex[e] > bp) { bp = ex[e]; best = e; }
        g_eidx[t] = best;
        g_prob[t] = bp / z;
    }
}

// ---------------- counting sort of tokens by expert ----------------
__global__ void k_zero()    { if (threadIdx.x < E_) g_cnt[threadIdx.x] = 0; }
__global__ void k_count()   { int t = blockIdx.x * 256 + threadIdx.x; if (t < T_) atomicAdd(&g_cnt[g_eidx[t]], 1); }
__global__ void k_offsets() {
    if (threadIdx.x == 0) {
        int a = 0;
        for (int e = 0; e < E_; e++) { g_off[e] = a; g_fill[e] = a; a += g_cnt[e]; }
        g_off[E_] = a;
    }
}
__global__ void k_scatter() {
    int t = blockIdx.x * 256 + threadIdx.x;
    if (t < T_) { int p = atomicAdd(&g_fill[g_eidx[t]], 1); g_perm[p] = t; }
}

// ---------------- MoE GEMM1: h1 = gelu(ln2[perm] * w1[e] + b1[e]) ----------------
__global__ void k_moe1(const float* __restrict__ w1, const float* __restrict__ b1) {
    int e = blockIdx.z;
    int beg = g_off[e], cnt = g_off[e + 1] - beg;
    int m0 = blockIdx.y * 64;
    if (m0 >= cnt) return;
    int n0 = blockIdx.x * 64;
    __shared__ float As[16][65], Bs[16][65];
    __shared__ int ridx[64];
    int tx = threadIdx.x, ty = threadIdx.y, tid = ty * 16 + tx;
    if (tid < 64) ridx[tid] = (m0 + tid < cnt) ? g_perm[beg + m0 + tid] : -1;
    __syncthreads();
    int lr = tid >> 2, lk = (tid & 3) * 4;     // A load (gathered rows)
    int bk = tid >> 4, bn4 = (tid & 15) * 4;   // B load (row-major)
    int tA = ridx[lr];
    const float* Arow  = (tA >= 0) ? g_ln2 + (size_t)tA * H_ + lk : g_ln2;
    const float* Bbase = w1 + (size_t)e * H_ * FF_;
    float acc[4][4] = {};
    for (int k0 = 0; k0 < H_; k0 += 16) {
        float4 av = (tA >= 0) ? *(const float4*)(Arow + k0) : make_float4(0.f, 0.f, 0.f, 0.f);
        float4 bv = *(const float4*)(Bbase + (size_t)(k0 + bk) * FF_ + n0 + bn4);
        As[lk + 0][lr] = av.x; As[lk + 1][lr] = av.y; As[lk + 2][lr] = av.z; As[lk + 3][lr] = av.w;
        Bs[bk][bn4 + 0] = bv.x; Bs[bk][bn4 + 1] = bv.y; Bs[bk][bn4 + 2] = bv.z; Bs[bk][bn4 + 3] = bv.w;
        __syncthreads();
#pragma unroll
        for (int kk = 0; kk < 16; kk++) {
            float a[4], b4[4];
#pragma unroll
            for (int i = 0; i < 4; i++) a[i]  = As[kk][ty * 4 + i];
#pragma unroll
            for (int j = 0; j < 4; j++) b4[j] = Bs[kk][tx * 4 + j];
#pragma unroll
            for (int i = 0; i < 4; i++)
#pragma unroll
                for (int j = 0; j < 4; j++) acc[i][j] = fmaf(a[i], b4[j], acc[i][j]);
        }
        __syncthreads();
    }
#pragma unroll
    for (int i = 0; i < 4; i++) {
        int rl = ty * 4 + i;
        if (ridx[rl] >= 0) {
            size_t ig = (size_t)(beg + m0 + rl);
#pragma unroll
            for (int j = 0; j < 4; j++) {
                int c = n0 + tx * 4 + j;
                float x = acc[i][j] + b1[(size_t)e * FF_ + c];
                float g = 0.5f * x * (1.0f + erff(x * 0.70710678118654752f));
                g_h1[ig * FF_ + c] = g;
            }
        }
    }
}

// ---------------- MoE GEMM2 + final residual: out = x1 + prob * (h1 * w2[e] + b2[e]) ----------------
__global__ void k_moe2(const float* __restrict__ w2, const float* __restrict__ b2,
                       float* __restrict__ out) {
    int e = blockIdx.z;
    int beg = g_off[e], cnt = g_off[e + 1] - beg;
    int m0 = blockIdx.y * 64;
    if (m0 >= cnt) return;
    int n0 = blockIdx.x * 64;
    __shared__ float As[16][65], Bs[16][65];
    __shared__ int ridx[64];
    int tx = threadIdx.x, ty = threadIdx.y, tid = ty * 16 + tx;
    if (tid < 64) ridx[tid] = (m0 + tid < cnt) ? g_perm[beg + m0 + tid] : -1;
    __syncthreads();
    int lr = tid >> 2, lk = (tid & 3) * 4;
    int bk = tid >> 4, bn4 = (tid & 15) * 4;
    bool aval = (m0 + lr) < cnt;
    size_t iA = (size_t)(beg + m0 + lr);
    const float* Bbase = w2 + (size_t)e * FF_ * H_;
    float acc[4][4] = {};
    for (int k0 = 0; k0 < FF_; k0 += 16) {
        float4 av = aval ? *(const float4*)(g_h1 + iA * FF_ + k0 + lk) : make_float4(0.f, 0.f, 0.f, 0.f);
        float4 bv = *(const float4*)(Bbase + (size_t)(k0 + bk) * H_ + n0 + bn4);
        As[lk + 0][lr] = av.x; As[lk + 1][lr] = av.y; As[lk + 2][lr] = av.z; As[lk + 3][lr] = av.w;
        Bs[bk][bn4 + 0] = bv.x; Bs[bk][bn4 + 1] = bv.y; Bs[bk][bn4 + 2] = bv.z; Bs[bk][bn4 + 3] = bv.w;
        __syncthreads();
#pragma unroll
        for (int kk = 0; kk < 16; kk++) {
            float a[4], b4[4];
#pragma unroll
            for (int i = 0; i < 4; i++) a[i]  = As[kk][ty * 4 + i];
#pragma unroll
            for (int j = 0; j < 4; j++) b4[j] = Bs[kk][tx * 4 + j];
#pragma unroll
            for (int i = 0; i < 4; i++)
#pragma unroll
                for (int j = 0; j < 4; j++) acc[i][j] = fmaf(a[i], b4[j], acc[i][j]);
        }
        __syncthreads();
    }
#pragma unroll
    for (int i = 0; i < 4; i++) {
        int rl = ty * 4 + i;
        int t = ridx[rl];
        if (t >= 0) {
            float p = g_prob[t];
#pragma unroll
            for (int j = 0; j < 4; j++) {
                int c = n0 + tx * 4 + j;
                out[(size_t)t * H_ + c] = g_x1[(size_t)t * H_ + c]
                                        + p * (acc[i][j] + b2[(size_t)e * H_ + c]);
            }
        }
    }
}

// ---------------- launch ----------------
extern "C" void kernel_launch(void* const* d_in, const int* in_sizes, int n_in,
                              void* d_out, int out_size) {
    const float* hidden = (const float*)d_in[0];
    // d_in[1] = attention_mask (causal, known at compile time; ignored)
    const float* ln1w = (const float*)d_in[2];
    const float* ln1b = (const float*)d_in[3];
    const float* qkvw = (const float*)d_in[4];
    const float* qkvb = (const float*)d_in[5];
    const float* dw   = (const float*)d_in[6];
    const float* db   = (const float*)d_in[7];
    const float* ln2w = (const float*)d_in[8];
    const float* ln2b = (const float*)d_in[9];
    const float* gw   = (const float*)d_in[10];
    const float* w1   = (const float*)d_in[11];
    const float* b1   = (const float*)d_in[12];
    const float* w2   = (const float*)d_in[13];
    const float* b2   = (const float*)d_in[14];
    float* out = (float*)d_out;

    cudaFuncSetAttribute(k_attn, cudaFuncAttributeMaxDynamicSharedMemorySize, 49408);

    k_ln1<<<T_, 256>>>(hidden, ln1w, ln1b);
    k_qkv<<<dim3(H3_ / 64, T_ / 64), dim3(16, 16)>>>(qkvw, qkvb);
    k_attn<<<dim3(S_ / 64, NH_, B_), dim3(16, 16), 49408>>>();
    k_dense<<<dim3(H_ / 64, T_ / 64), dim3(16, 16)>>>(dw, db, hidden);
    k_ln2<<<T_, 256>>>(ln2w, ln2b);
    k_gate<<<T_ / 4, 128>>>(gw);
    k_zero<<<1, 32>>>();
    k_count<<<T_ / 256, 256>>>();
    k_offsets<<<1, 32>>>();
    k_scatter<<<T_ / 256, 256>>>();
    k_moe1<<<dim3(FF_ / 64, T_ / 64, E_), dim3(16, 16)>>>(w1, b1);
    k_moe2<<<dim3(H_ / 64, T_ / 64, E_), dim3(16, 16)>>>(w2, b2, out);
}

// round 6
// speedup vs baseline: 1.3180x; 1.3180x over previous
#include <cuda_runtime.h>
#include <cstdint>
#include <math.h>

#define S_  1024
#define B_  4
#define H_  768
#define NH_ 12
#define HD_ 64
#define FF_ 3072
#define E_  4
#define T_  4096
#define H3_ 2304

// ======================= scratch =======================
__device__ float g_ln1[(size_t)T_ * H_];
__device__ float g_qkv[(size_t)T_ * H3_];
__device__ float g_ctx[(size_t)T_ * H_];
__device__ float g_x1 [(size_t)T_ * H_];
__device__ float g_ln2[(size_t)T_ * H_];
__device__ float g_h1 [(size_t)T_ * FF_];
__device__ int   g_eidx[T_];
__device__ float g_prob[T_];
__device__ int   g_perm[T_];
__device__ int   g_cnt [E_];
__device__ int   g_off [E_ + 1];
__device__ int   g_fill[E_];

// ======================= layernorm =======================
__device__ __forceinline__ void ln_row(const float* __restrict__ x, float* __restrict__ y,
                                       const float* __restrict__ w, const float* __restrict__ b) {
    __shared__ float red[2][8];
    int tid = threadIdx.x;
    float v0 = x[tid], v1 = x[tid + 256], v2 = x[tid + 512];
    float s  = v0 + v1 + v2;
    float ss = v0 * v0 + v1 * v1 + v2 * v2;
    for (int o = 16; o; o >>= 1) {
        s  += __shfl_xor_sync(0xffffffffu, s,  o);
        ss += __shfl_xor_sync(0xffffffffu, ss, o);
    }
    if ((tid & 31) == 0) { red[0][tid >> 5] = s; red[1][tid >> 5] = ss; }
    __syncthreads();
    if (tid < 32) {
        float a = (tid < 8) ? red[0][tid] : 0.f;
        float c = (tid < 8) ? red[1][tid] : 0.f;
        for (int o = 4; o; o >>= 1) {
            a += __shfl_xor_sync(0xffffffffu, a, o);
            c += __shfl_xor_sync(0xffffffffu, c, o);
        }
        if (tid == 0) { red[0][0] = a; red[1][0] = c; }
    }
    __syncthreads();
    float mean = red[0][0] * (1.0f / H_);
    float var  = red[1][0] * (1.0f / H_) - mean * mean;
    float inv  = rsqrtf(var + 1e-5f);
    y[tid]       = (v0 - mean) * inv * w[tid]       + b[tid];
    y[tid + 256] = (v1 - mean) * inv * w[tid + 256] + b[tid + 256];
    y[tid + 512] = (v2 - mean) * inv * w[tid + 512] + b[tid + 512];
}

__global__ void k_ln1(const float* __restrict__ hidden,
                      const float* __restrict__ w, const float* __restrict__ b) {
    ln_row(hidden + (size_t)blockIdx.x * H_, g_ln1 + (size_t)blockIdx.x * H_, w, b);
}
__global__ void k_ln2(const float* __restrict__ w, const float* __restrict__ b) {
    ln_row(g_x1 + (size_t)blockIdx.x * H_, g_ln2 + (size_t)blockIdx.x * H_, w, b);
}

// ======================= fast SIMT GEMM: 128x128 tile, 8x8 per thread =======================
// A [M][K] row-major (gathered for MODE 2, compact for MODE 3).
// MODE 0/1: B = W[N][K] (transposed store into smem).  MODE 2/3: B = W[K][N] (direct).
// MODE 0: g_qkv = acc + bias
// MODE 1: g_x1  = extra + acc + bias
// MODE 2: g_h1  = gelu(acc + bias[e*FF+n])
// MODE 3: out   = g_x1[t] + prob[t] * (acc + bias[e*H+n])
template<int MODE, int KDIM, int NSTR>
__global__ void __launch_bounds__(256) k_sgemm(const float* __restrict__ Bsrc,
                                               const float* __restrict__ bias,
                                               const float* __restrict__ extra,
                                               float* __restrict__ outp) {
    constexpr bool TRB = (MODE < 2);
    __shared__ float As[16][132];
    __shared__ float Bs[16][132];
    __shared__ int sridx[128];

    const int tid = threadIdx.x;
    const int tx = tid & 15, ty = tid >> 4;
    const int n0 = blockIdx.x * 128;
    const int m0 = blockIdx.y * 128;
    const int e  = (MODE >= 2) ? blockIdx.z : 0;

    int beg = 0, cnt = T_;
    if (MODE >= 2) {
        beg = g_off[e]; cnt = g_off[e + 1] - beg;
        if (m0 >= cnt) return;
    }

    const float* Abase = (MODE == 0) ? g_ln1 : (MODE == 1) ? g_ctx
                        : (MODE == 2) ? g_ln2 : g_h1;
    const float* Bbase = Bsrc;
    if (MODE == 2) Bbase += (size_t)e * H_ * FF_;
    if (MODE == 3) Bbase += (size_t)e * FF_ * H_;

    if (MODE >= 2 && tid < 128)
        sridx[tid] = (m0 + tid < cnt) ? g_perm[beg + m0 + tid] : -1;
    if (MODE >= 2) __syncthreads();

    // ---- A loader: rows ar, ar+64; k-chunk ac*4 (transposed store As[k][m]) ----
    const int ar = tid >> 2;          // 0..63
    const int ac = tid & 3;           // 0..3
    const int arows[2] = { ar, ar + 64 };
    const float* pA[2];
    bool avA[2];
#pragma unroll
    for (int i = 0; i < 2; i++) {
        int r = arows[i];
        long grow = m0 + r;
        avA[i] = true;
        if (MODE == 2) { int t = sridx[r]; avA[i] = (t >= 0); grow = avA[i] ? t : 0; }
        if (MODE == 3) { avA[i] = (m0 + r < cnt); grow = avA[i] ? (beg + m0 + r) : 0; }
        pA[i] = Abase + (size_t)grow * KDIM + ac * 4;
    }
    // ---- B loader ----
    const float* pB[2];             // TRB: rows n0+ar, n0+ar+64
    const float* pBn = nullptr;     // !TRB: row bk, n-chunks bc*4 and bc*4+64
    const int bk = tid >> 4;        // 0..15
    const int bc = tid & 15;        // 0..15
    if (TRB) {
#pragma unroll
        for (int i = 0; i < 2; i++)
            pB[i] = Bbase + (size_t)(n0 + arows[i]) * KDIM + ac * 4;
    } else {
        pBn = Bbase + (size_t)bk * NSTR + n0 + bc * 4;
    }

    float4 ra[2], rb[2];
    const float4 fz = make_float4(0.f, 0.f, 0.f, 0.f);

    // initial load (k0 = 0)
#pragma unroll
    for (int i = 0; i < 2; i++) {
        ra[i] = avA[i] ? *(const float4*)(pA[i]) : fz;
        if (TRB) rb[i] = *(const float4*)(pB[i]);
    }
    if (!TRB) {
        rb[0] = *(const float4*)(pBn);
        rb[1] = *(const float4*)(pBn + 64);
    }
#pragma unroll
    for (int i = 0; i < 2; i++) {
        const float* v = (const float*)&ra[i];
        As[ac * 4 + 0][arows[i]] = v[0];
        As[ac * 4 + 1][arows[i]] = v[1];
        As[ac * 4 + 2][arows[i]] = v[2];
        As[ac * 4 + 3][arows[i]] = v[3];
    }
    if (TRB) {
#pragma unroll
        for (int i = 0; i < 2; i++) {
            const float* v = (const float*)&rb[i];
            Bs[ac * 4 + 0][arows[i]] = v[0];
            Bs[ac * 4 + 1][arows[i]] = v[1];
            Bs[ac * 4 + 2][arows[i]] = v[2];
            Bs[ac * 4 + 3][arows[i]] = v[3];
        }
    } else {
        *(float4*)&Bs[bk][bc * 4]      = rb[0];
        *(float4*)&Bs[bk][bc * 4 + 64] = rb[1];
    }
    __syncthreads();

    float acc[8][8] = {};

    for (int k0 = 0; k0 < KDIM; k0 += 16) {
        const bool more = (k0 + 16) < KDIM;
        if (more) {
            int kn = k0 + 16;
#pragma unroll
            for (int i = 0; i < 2; i++) {
                ra[i] = avA[i] ? *(const float4*)(pA[i] + kn) : fz;
                if (TRB) rb[i] = *(const float4*)(pB[i] + kn);
            }
            if (!TRB) {
                rb[0] = *(const float4*)(pBn + (size_t)kn * NSTR);
                rb[1] = *(const float4*)(pBn + (size_t)kn * NSTR + 64);
            }
        }
#pragma unroll
        for (int kk = 0; kk < 16; kk++) {
            float a[8], b[8];
            *(float4*)&a[0] = *(const float4*)&As[kk][ty * 8];
            *(float4*)&a[4] = *(const float4*)&As[kk][ty * 8 + 4];
            *(float4*)&b[0] = *(const float4*)&Bs[kk][tx * 8];
            *(float4*)&b[4] = *(const float4*)&Bs[kk][tx * 8 + 4];
#pragma unroll
            for (int i = 0; i < 8; i++)
#pragma unroll
                for (int j = 0; j < 8; j++)
                    acc[i][j] = fmaf(a[i], b[j], acc[i][j]);
        }
        if (more) {
            __syncthreads();
#pragma unroll
            for (int i = 0; i < 2; i++) {
                const float* v = (const float*)&ra[i];
                As[ac * 4 + 0][arows[i]] = v[0];
                As[ac * 4 + 1][arows[i]] = v[1];
                As[ac * 4 + 2][arows[i]] = v[2];
                As[ac * 4 + 3][arows[i]] = v[3];
            }
            if (TRB) {
#pragma unroll
                for (int i = 0; i < 2; i++) {
                    const float* v = (const float*)&rb[i];
                    Bs[ac * 4 + 0][arows[i]] = v[0];
                    Bs[ac * 4 + 1][arows[i]] = v[1];
                    Bs[ac * 4 + 2][arows[i]] = v[2];
                    Bs[ac * 4 + 3][arows[i]] = v[3];
                }
            } else {
                *(float4*)&Bs[bk][bc * 4]      = rb[0];
                *(float4*)&Bs[bk][bc * 4 + 64] = rb[1];
            }
            __syncthreads();
        }
    }

    // ---- epilogue ----
#pragma unroll
    for (int i = 0; i < 8; i++) {
        const int rl = ty * 8 + i;
        bool valid = true;
        int tkn = 0; float pgate = 0.f;
        if (MODE == 2) valid = (m0 + rl) < cnt;
        if (MODE == 3) { tkn = sridx[rl]; valid = (tkn >= 0); if (valid) pgate = g_prob[tkn]; }
        if (!valid) continue;
#pragma unroll
        for (int j = 0; j < 8; j++) {
            const int n = n0 + tx * 8 + j;
            const float v = acc[i][j];
            if (MODE == 0) {
                g_qkv[(size_t)(m0 + rl) * H3_ + n] = v + bias[n];
            } else if (MODE == 1) {
                size_t o = (size_t)(m0 + rl) * H_ + n;
                g_x1[o] = extra[o] + v + bias[n];
            } else if (MODE == 2) {
                float x = v + bias[(size_t)e * FF_ + n];
                float g = 0.5f * x * (1.0f + erff(x * 0.70710678118654752f));
                g_h1[(size_t)(beg + m0 + rl) * FF_ + n] = g;
            } else {
                size_t o = (size_t)tkn * H_ + n;
                outp[o] = g_x1[o] + pgate * (v + bias[(size_t)e * H_ + n]);
            }
        }
    }
}

// ======================= causal flash attention (SIMT fp32, R0 proven) =======================
__global__ void k_attn() {
    extern __shared__ float sm[];
    float* Qs = sm;
    float* KP = sm + 4096;
    float* Vs = sm + 4096 + 4160;
    int qt = blockIdx.x, n = blockIdx.y, b = blockIdx.z;
    int tx = threadIdx.x, ty = threadIdx.y, tid = ty * 16 + tx;
    int q0 = qt * 64;
    const float SCALE = 0.125f;
    {
        int r = tid >> 4, d4 = (tid & 15) * 4;
        for (int rr = r; rr < 64; rr += 16) {
            float4 v = *(const float4*)(g_qkv + ((size_t)(q0 + rr) * B_ + b) * H3_ + n * 192 + d4);
            float* dst = Qs + rr * 64 + d4;
            dst[0] = v.x * SCALE; dst[1] = v.y * SCALE; dst[2] = v.z * SCALE; dst[3] = v.w * SCALE;
        }
    }
    float o[4][4] = {};
    float m_run[4] = {-1e30f, -1e30f, -1e30f, -1e30f};
    float l_run[4] = {0.f, 0.f, 0.f, 0.f};

    for (int j = 0; j <= qt; ++j) {
        __syncthreads();
        int k0 = j * 64;
        {
            int r = tid >> 4, d4 = (tid & 15) * 4;
            for (int rr = r; rr < 64; rr += 16) {
                const float* base = g_qkv + ((size_t)(k0 + rr) * B_ + b) * H3_ + n * 192;
                float4 kv = *(const float4*)(base + 64 + d4);
                KP[rr * 65 + d4 + 0] = kv.x; KP[rr * 65 + d4 + 1] = kv.y;
                KP[rr * 65 + d4 + 2] = kv.z; KP[rr * 65 + d4 + 3] = kv.w;
                float4 vv = *(const float4*)(base + 128 + d4);
                *(float4*)(Vs + rr * 64 + d4) = vv;
            }
        }
        __syncthreads();
        float sacc[4][4] = {};
#pragma unroll 8
        for (int d = 0; d < 64; ++d) {
            float a[4], kr[4];
#pragma unroll
            for (int i = 0; i < 4; i++) a[i]  = Qs[(ty * 4 + i) * 64 + d];
#pragma unroll
            for (int c = 0; c < 4; c++) kr[c] = KP[(tx * 4 + c) * 65 + d];
#pragma unroll
            for (int i = 0; i < 4; i++)
#pragma unroll
                for (int c = 0; c < 4; c++) sacc[i][c] = fmaf(a[i], kr[c], sacc[i][c]);
        }
        if (j == qt) {
#pragma unroll
            for (int i = 0; i < 4; i++)
#pragma unroll
                for (int c = 0; c < 4; c++)
                    if (tx * 4 + c > ty * 4 + i) sacc[i][c] = -1e30f;
        }
        float mx[4], mnew[4], scl[4], rs[4];
#pragma unroll
        for (int i = 0; i < 4; i++) {
            mx[i] = fmaxf(fmaxf(sacc[i][0], sacc[i][1]), fmaxf(sacc[i][2], sacc[i][3]));
            for (int oo = 8; oo; oo >>= 1)
                mx[i] = fmaxf(mx[i], __shfl_xor_sync(0xffffffffu, mx[i], oo));
            mnew[i] = fmaxf(m_run[i], mx[i]);
            scl[i]  = expf(m_run[i] - mnew[i]);
            m_run[i] = mnew[i];
            rs[i] = 0.f;
#pragma unroll
            for (int c = 0; c < 4; c++) {
                sacc[i][c] = expf(sacc[i][c] - mnew[i]);
                rs[i] += sacc[i][c];
            }
            for (int oo = 8; oo; oo >>= 1)
                rs[i] += __shfl_xor_sync(0xffffffffu, rs[i], oo);
            l_run[i] = l_run[i] * scl[i] + rs[i];
#pragma unroll
            for (int c = 0; c < 4; c++) o[i][c] *= scl[i];
        }
        __syncthreads();
#pragma unroll
        for (int i = 0; i < 4; i++)
#pragma unroll
            for (int c = 0; c < 4; c++)
                KP[(ty * 4 + i) * 65 + tx * 4 + c] = sacc[i][c];
        __syncthreads();
#pragma unroll 8
        for (int d = 0; d < 64; ++d) {
            float pi[4], vj[4];
#pragma unroll
            for (int i = 0; i < 4; i++) pi[i] = KP[(ty * 4 + i) * 65 + d];
#pragma unroll
            for (int c = 0; c < 4; c++) vj[c] = Vs[d * 64 + tx * 4 + c];
#pragma unroll
            for (int i = 0; i < 4; i++)
#pragma unroll
                for (int c = 0; c < 4; c++) o[i][c] = fmaf(pi[i], vj[c], o[i][c]);
        }
    }
#pragma unroll
    for (int i = 0; i < 4; i++) {
        float invl = 1.0f / l_run[i];
#pragma unroll
        for (int c = 0; c < 4; c++)
            g_ctx[((size_t)(q0 + ty * 4 + i) * B_ + b) * H_ + n * HD_ + tx * 4 + c] = o[i][c] * invl;
    }
}

// ======================= gate + routing =======================
__global__ void k_gate(const float* __restrict__ gw) {
    int gidx = blockIdx.x * blockDim.x + threadIdx.x;
    int t = gidx >> 5, lane = gidx & 31;
    if (t >= T_) return;
    const float* x = g_ln2 + (size_t)t * H_;
    float s0 = 0, s1 = 0, s2 = 0, s3 = 0;
    for (int h = lane; h < H_; h += 32) {
        float xv = x[h];
        s0 = fmaf(xv, gw[h],          s0);
        s1 = fmaf(xv, gw[H_ + h],     s1);
        s2 = fmaf(xv, gw[2 * H_ + h], s2);
        s3 = fmaf(xv, gw[3 * H_ + h], s3);
    }
    for (int o = 16; o; o >>= 1) {
        s0 += __shfl_xor_sync(0xffffffffu, s0, o);
        s1 += __shfl_xor_sync(0xffffffffu, s1, o);
        s2 += __shfl_xor_sync(0xffffffffu, s2, o);
        s3 += __shfl_xor_sync(0xffffffffu, s3, o);
    }
    if (lane == 0) {
        float l[4] = {s0, s1, s2, s3};
        float mx = fmaxf(fmaxf(l[0], l[1]), fmaxf(l[2], l[3]));
        float ex[4], z = 0.f;
        for (int e = 0; e < 4; e++) { ex[e] = expf(l[e] - mx); z += ex[e]; }
        int best = 0; float bp = ex[0];
        for (int e = 1; e < 4; e++) if (ex[e] > bp) { bp = ex[e]; best = e; }
        g_eidx[t] = best;
        g_prob[t] = bp / z;
    }
}
__global__ void k_zero()  { if (threadIdx.x < E_) g_cnt[threadIdx.x] = 0; }
__global__ void k_count() { int t = blockIdx.x * 256 + threadIdx.x; if (t < T_) atomicAdd(&g_cnt[g_eidx[t]], 1); }
__global__ void k_offsets() {
    if (threadIdx.x == 0) {
        int a = 0;
        for (int e = 0; e < E_; e++) { g_off[e] = a; g_fill[e] = a; a += g_cnt[e]; }
        g_off[E_] = a;
    }
}
__global__ void k_scatter() {
    int t = blockIdx.x * 256 + threadIdx.x;
    if (t < T_) { int p = atomicAdd(&g_fill[g_eidx[t]], 1); g_perm[p] = t; }
}

// ======================= launch =======================
extern "C" void kernel_launch(void* const* d_in, const int* in_sizes, int n_in,
                              void* d_out, int out_size) {
    const float* hidden = (const float*)d_in[0];
    const float* ln1w = (const float*)d_in[2];
    const float* ln1b = (const float*)d_in[3];
    const float* qkvw = (const float*)d_in[4];
    const float* qkvb = (const float*)d_in[5];
    const float* dw   = (const float*)d_in[6];
    const float* db   = (const float*)d_in[7];
    const float* ln2w = (const float*)d_in[8];
    const float* ln2b = (const float*)d_in[9];
    const float* gw   = (const float*)d_in[10];
    const float* w1   = (const float*)d_in[11];
    const float* b1   = (const float*)d_in[12];
    const float* w2   = (const float*)d_in[13];
    const float* b2   = (const float*)d_in[14];
    float* out = (float*)d_out;

    cudaFuncSetAttribute(k_attn, cudaFuncAttributeMaxDynamicSharedMemorySize, 49408);

    k_ln1<<<T_, 256>>>(hidden, ln1w, ln1b);
    k_sgemm<0, 768, 1><<<dim3(H3_ / 128, T_ / 128), 256>>>(qkvw, qkvb, nullptr, nullptr);
    k_attn<<<dim3(S_ / 64, NH_, B_), dim3(16, 16), 49408>>>();
    k_sgemm<1, 768, 1><<<dim3(H_ / 128, T_ / 128), 256>>>(dw, db, hidden, nullptr);
    k_ln2<<<T_, 256>>>(ln2w, ln2b);
    k_gate<<<T_ / 4, 128>>>(gw);
    k_zero<<<1, 32>>>();
    k_count<<<T_ / 256, 256>>>();
    k_offsets<<<1, 32>>>();
    k_scatter<<<T_ / 256, 256>>>();
    k_sgemm<2, 768, FF_><<<dim3(FF_ / 128, T_ / 128, E_), 256>>>(w1, b1, nullptr, nullptr);
    k_sgemm<3, 3072, H_><<<dim3(H_ / 128, T_ / 128, E_), 256>>>(w2, b2, nullptr, out);
}

// round 7
// speedup vs baseline: 1.4437x; 1.0954x over previous
#include <cuda_runtime.h>
#include <cstdint>
#include <math.h>

#define S_  1024
#define B_  4
#define H_  768
#define NH_ 12
#define HD_ 64
#define FF_ 3072
#define E_  4
#define T_  4096
#define H3_ 2304
#define PITCH 136   // smem row pitch (floats): bank = 8*k + m (mod 32), conflict-free frags

// ======================= scratch =======================
__device__ float g_ln1[(size_t)T_ * H_];
__device__ float g_qkv[(size_t)T_ * H3_];
__device__ float g_ctx[(size_t)T_ * H_];
__device__ float g_x1 [(size_t)T_ * H_];
__device__ float g_ln2[(size_t)T_ * H_];
__device__ float g_h1 [(size_t)T_ * FF_];
__device__ int   g_eidx[T_];
__device__ float g_prob[T_];
__device__ int   g_perm[T_];
__device__ int   g_cnt [E_];
__device__ int   g_off [E_ + 1];
__device__ int   g_fill[E_];

// ======================= tf32 helpers =======================
__device__ __forceinline__ void tf32split(float x, uint32_t& hi, uint32_t& lo) {
    asm("cvt.rna.tf32.f32 %0, %1;" : "=r"(hi) : "f"(x));
    float r = x - __uint_as_float(hi);
    asm("cvt.rna.tf32.f32 %0, %1;" : "=r"(lo) : "f"(r));
}
#define MMAT(d, a, b) \
    asm volatile("mma.sync.aligned.m16n8k8.row.col.f32.tf32.tf32.f32 " \
        "{%0,%1,%2,%3}, {%4,%5,%6,%7}, {%8,%9}, {%0,%1,%2,%3};" \
        : "+f"((d)[0]), "+f"((d)[1]), "+f"((d)[2]), "+f"((d)[3]) \
        : "r"((a)[0]), "r"((a)[1]), "r"((a)[2]), "r"((a)[3]), "r"((b)[0]), "r"((b)[1]))

// ======================= layernorm =======================
__device__ __forceinline__ void ln_row(const float* __restrict__ x, float* __restrict__ y,
                                       const float* __restrict__ w, const float* __restrict__ b) {
    __shared__ float red[2][8];
    int tid = threadIdx.x;
    float v0 = x[tid], v1 = x[tid + 256], v2 = x[tid + 512];
    float s  = v0 + v1 + v2;
    float ss = v0 * v0 + v1 * v1 + v2 * v2;
    for (int o = 16; o; o >>= 1) {
        s  += __shfl_xor_sync(0xffffffffu, s,  o);
        ss += __shfl_xor_sync(0xffffffffu, ss, o);
    }
    if ((tid & 31) == 0) { red[0][tid >> 5] = s; red[1][tid >> 5] = ss; }
    __syncthreads();
    if (tid < 32) {
        float a = (tid < 8) ? red[0][tid] : 0.f;
        float c = (tid < 8) ? red[1][tid] : 0.f;
        for (int o = 4; o; o >>= 1) {
            a += __shfl_xor_sync(0xffffffffu, a, o);
            c += __shfl_xor_sync(0xffffffffu, c, o);
        }
        if (tid == 0) { red[0][0] = a; red[1][0] = c; }
    }
    __syncthreads();
    float mean = red[0][0] * (1.0f / H_);
    float var  = red[1][0] * (1.0f / H_) - mean * mean;
    float inv  = rsqrtf(var + 1e-5f);
    y[tid]       = (v0 - mean) * inv * w[tid]       + b[tid];
    y[tid + 256] = (v1 - mean) * inv * w[tid + 256] + b[tid + 256];
    y[tid + 512] = (v2 - mean) * inv * w[tid + 512] + b[tid + 512];
}

__global__ void k_ln1(const float* __restrict__ hidden,
                      const float* __restrict__ w, const float* __restrict__ b) {
    ln_row(hidden + (size_t)blockIdx.x * H_, g_ln1 + (size_t)blockIdx.x * H_, w, b);
}
__global__ void k_ln2(const float* __restrict__ w, const float* __restrict__ b) {
    ln_row(g_x1 + (size_t)blockIdx.x * H_, g_ln2 + (size_t)blockIdx.x * H_, w, b);
}

// ======================= 3xTF32 tensor-core GEMM =======================
// 128x128 CTA tile, 8 warps (2x4), warp tile 64x32, BK=16 (2x k8 mma steps).
// fp32 in smem (As[k][m], Bs[k][n]); per-fragment tf32 hi/lo split;
// D += Ahi*Bhi + Ahi*Blo + Alo*Bhi  (error ~2^-21 per product -> ~1e-6 output).
// A [M][K] row-major (MODE 2 gathered rows, MODE 3 compact rows).
// MODE 0/1: B = W[N][K] (transposed store).  MODE 2/3: B = W[K][N] (direct).
template<int MODE, int KDIM, int NSTR>
__global__ void __launch_bounds__(256) k_tgemm(const float* __restrict__ Bsrc,
                                               const float* __restrict__ bias,
                                               const float* __restrict__ extra,
                                               float* __restrict__ outp) {
    constexpr bool TRB = (MODE < 2);
    __shared__ float As[16][PITCH];
    __shared__ float Bs[16][PITCH];
    __shared__ int sridx[128];

    const int tid = threadIdx.x;
    const int n0 = blockIdx.x * 128;
    const int m0 = blockIdx.y * 128;
    const int e  = (MODE >= 2) ? blockIdx.z : 0;

    int beg = 0, cnt = T_;
    if (MODE >= 2) {
        beg = g_off[e]; cnt = g_off[e + 1] - beg;
        if (m0 >= cnt) return;
    }

    const float* Abase = (MODE == 0) ? g_ln1 : (MODE == 1) ? g_ctx
                        : (MODE == 2) ? g_ln2 : g_h1;
    const float* Bbase = Bsrc;
    if (MODE == 2) Bbase += (size_t)e * H_ * FF_;
    if (MODE == 3) Bbase += (size_t)e * FF_ * H_;

    if (MODE >= 2 && tid < 128)
        sridx[tid] = (m0 + tid < cnt) ? g_perm[beg + m0 + tid] : -1;
    if (MODE >= 2) __syncthreads();

    // ---- loaders (structure identical to proven R6 kernel) ----
    const int ar = tid >> 2;          // 0..63
    const int ac = tid & 3;           // 0..3
    const int arows[2] = { ar, ar + 64 };
    const float* pA[2];
    bool avA[2];
#pragma unroll
    for (int i = 0; i < 2; i++) {
        int r = arows[i];
        long grow = m0 + r;
        avA[i] = true;
        if (MODE == 2) { int t = sridx[r]; avA[i] = (t >= 0); grow = avA[i] ? t : 0; }
        if (MODE == 3) { avA[i] = (m0 + r < cnt); grow = avA[i] ? (beg + m0 + r) : 0; }
        pA[i] = Abase + (size_t)grow * KDIM + ac * 4;
    }
    const float* pB[2];             // TRB
    const float* pBn = nullptr;     // !TRB
    const int bk = tid >> 4;        // 0..15
    const int bc = tid & 15;        // 0..15
    if (TRB) {
#pragma unroll
        for (int i = 0; i < 2; i++)
            pB[i] = Bbase + (size_t)(n0 + arows[i]) * KDIM + ac * 4;
    } else {
        pBn = Bbase + (size_t)bk * NSTR + n0 + bc * 4;
    }

    float4 ra[2], rb[2];
    const float4 fz = make_float4(0.f, 0.f, 0.f, 0.f);

    // initial load k0=0
#pragma unroll
    for (int i = 0; i < 2; i++) {
        ra[i] = avA[i] ? *(const float4*)(pA[i]) : fz;
        if (TRB) rb[i] = *(const float4*)(pB[i]);
    }
    if (!TRB) {
        rb[0] = *(const float4*)(pBn);
        rb[1] = *(const float4*)(pBn + 64);
    }
#pragma unroll
    for (int i = 0; i < 2; i++) {
        const float* v = (const float*)&ra[i];
        As[ac * 4 + 0][arows[i]] = v[0];
        As[ac * 4 + 1][arows[i]] = v[1];
        As[ac * 4 + 2][arows[i]] = v[2];
        As[ac * 4 + 3][arows[i]] = v[3];
    }
    if (TRB) {
#pragma unroll
        for (int i = 0; i < 2; i++) {
            const float* v = (const float*)&rb[i];
            Bs[ac * 4 + 0][arows[i]] = v[0];
            Bs[ac * 4 + 1][arows[i]] = v[1];
            Bs[ac * 4 + 2][arows[i]] = v[2];
            Bs[ac * 4 + 3][arows[i]] = v[3];
        }
    } else {
        *(float4*)&Bs[bk][bc * 4]      = rb[0];
        *(float4*)&Bs[bk][bc * 4 + 64] = rb[1];
    }
    __syncthreads();

    // ---- fragment coords ----
    const int wid = tid >> 5, lane = tid & 31;
    const int wm = wid >> 2, wn = wid & 3;   // warp tile (wm*64, wn*32)
    const int fr = lane >> 2;                // 0..7
    const int fc = lane & 3;                 // 0..3

    float acc[4][4][4] = {};

    for (int k0 = 0; k0 < KDIM; k0 += 16) {
        const bool more = (k0 + 16) < KDIM;
        if (more) {
            int kn = k0 + 16;
#pragma unroll
            for (int i = 0; i < 2; i++) {
                ra[i] = avA[i] ? *(const float4*)(pA[i] + kn) : fz;
                if (TRB) rb[i] = *(const float4*)(pB[i] + kn);
            }
            if (!TRB) {
                rb[0] = *(const float4*)(pBn + (size_t)kn * NSTR);
                rb[1] = *(const float4*)(pBn + (size_t)kn * NSTR + 64);
            }
        }
        // ---- compute: 2 x k8 mma steps ----
#pragma unroll
        for (int ks = 0; ks < 2; ks++) {
            const int kofs = ks * 8;
            uint32_t ahi[4][4], alo[4][4];
#pragma unroll
            for (int mi = 0; mi < 4; mi++) {
                const int mb = wm * 64 + mi * 16 + fr;
                // A frag (m16k8): a0=(r,c) a1=(r+8,c) a2=(r,c+4) a3=(r+8,c+4)
                tf32split(As[kofs + fc    ][mb    ], ahi[mi][0], alo[mi][0]);
                tf32split(As[kofs + fc    ][mb + 8], ahi[mi][1], alo[mi][1]);
                tf32split(As[kofs + fc + 4][mb    ], ahi[mi][2], alo[mi][2]);
                tf32split(As[kofs + fc + 4][mb + 8], ahi[mi][3], alo[mi][3]);
            }
#pragma unroll
            for (int ni = 0; ni < 4; ni++) {
                const int nb = wn * 32 + ni * 8 + fr;
                // B frag (k8n8): b0=(k=c, n=r) b1=(k=c+4, n=r)
                uint32_t bhi[2], blo[2];
                tf32split(Bs[kofs + fc    ][nb], bhi[0], blo[0]);
                tf32split(Bs[kofs + fc + 4][nb], bhi[1], blo[1]);
#pragma unroll
                for (int mi = 0; mi < 4; mi++) {
                    MMAT(acc[mi][ni], ahi[mi], bhi);
                    MMAT(acc[mi][ni], ahi[mi], blo);
                    MMAT(acc[mi][ni], alo[mi], bhi);
                }
            }
        }
        if (more) {
            __syncthreads();
#pragma unroll
            for (int i = 0; i < 2; i++) {
                const float* v = (const float*)&ra[i];
                As[ac * 4 + 0][arows[i]] = v[0];
                As[ac * 4 + 1][arows[i]] = v[1];
                As[ac * 4 + 2][arows[i]] = v[2];
                As[ac * 4 + 3][arows[i]] = v[3];
            }
            if (TRB) {
#pragma unroll
                for (int i = 0; i < 2; i++) {
                    const float* v = (const float*)&rb[i];
                    Bs[ac * 4 + 0][arows[i]] = v[0];
                    Bs[ac * 4 + 1][arows[i]] = v[1];
                    Bs[ac * 4 + 2][arows[i]] = v[2];
                    Bs[ac * 4 + 3][arows[i]] = v[3];
                }
            } else {
                *(float4*)&Bs[bk][bc * 4]      = rb[0];
                *(float4*)&Bs[bk][bc * 4 + 64] = rb[1];
            }
            __syncthreads();
        }
    }

    // ---- epilogue: C frag rows lane>>2 (+8), cols 2*(lane&3) (+1) ----
#pragma unroll
    for (int mi = 0; mi < 4; mi++) {
#pragma unroll
        for (int half = 0; half < 2; half++) {
            const int rl = wm * 64 + mi * 16 + fr + half * 8;
            bool valid = true;
            int tkn = 0; float pgate = 0.f;
            if (MODE == 2) valid = (m0 + rl) < cnt;
            if (MODE == 3) { tkn = sridx[rl]; valid = (tkn >= 0); if (valid) pgate = g_prob[tkn]; }
            if (!valid) continue;
#pragma unroll
            for (int ni = 0; ni < 4; ni++) {
                const int n = n0 + wn * 32 + ni * 8 + fc * 2;
                const float v0 = acc[mi][ni][half * 2 + 0];
                const float v1 = acc[mi][ni][half * 2 + 1];
                if (MODE == 0) {
                    size_t o = (size_t)(m0 + rl) * H3_ + n;
                    g_qkv[o]     = v0 + bias[n];
                    g_qkv[o + 1] = v1 + bias[n + 1];
                } else if (MODE == 1) {
                    size_t o = (size_t)(m0 + rl) * H_ + n;
                    g_x1[o]     = extra[o]     + v0 + bias[n];
                    g_x1[o + 1] = extra[o + 1] + v1 + bias[n + 1];
                } else if (MODE == 2) {
                    size_t o = (size_t)(beg + m0 + rl) * FF_ + n;
                    float x0 = v0 + bias[(size_t)e * FF_ + n];
                    float x1 = v1 + bias[(size_t)e * FF_ + n + 1];
                    g_h1[o]     = 0.5f * x0 * (1.0f + erff(x0 * 0.70710678118654752f));
                    g_h1[o + 1] = 0.5f * x1 * (1.0f + erff(x1 * 0.70710678118654752f));
                } else {
                    size_t o = (size_t)tkn * H_ + n;
                    outp[o]     = g_x1[o]     + pgate * (v0 + bias[(size_t)e * H_ + n]);
                    outp[o + 1] = g_x1[o + 1] + pgate * (v1 + bias[(size_t)e * H_ + n + 1]);
                }
            }
        }
    }
}

// ======================= causal flash attention (SIMT fp32, proven) =======================
__global__ void k_attn() {
    extern __shared__ float sm[];
    float* Qs = sm;
    float* KP = sm + 4096;
    float* Vs = sm + 4096 + 4160;
    int qt = blockIdx.x, n = blockIdx.y, b = blockIdx.z;
    int tx = threadIdx.x, ty = threadIdx.y, tid = ty * 16 + tx;
    int q0 = qt * 64;
    const float SCALE = 0.125f;
    {
        int r = tid >> 4, d4 = (tid & 15) * 4;
        for (int rr = r; rr < 64; rr += 16) {
            float4 v = *(const float4*)(g_qkv + ((size_t)(q0 + rr) * B_ + b) * H3_ + n * 192 + d4);
            float* dst = Qs + rr * 64 + d4;
            dst[0] = v.x * SCALE; dst[1] = v.y * SCALE; dst[2] = v.z * SCALE; dst[3] = v.w * SCALE;
        }
    }
    float o[4][4] = {};
    float m_run[4] = {-1e30f, -1e30f, -1e30f, -1e30f};
    float l_run[4] = {0.f, 0.f, 0.f, 0.f};

    for (int j = 0; j <= qt; ++j) {
        __syncthreads();
        int k0 = j * 64;
        {
            int r = tid >> 4, d4 = (tid & 15) * 4;
            for (int rr = r; rr < 64; rr += 16) {
                const float* base = g_qkv + ((size_t)(k0 + rr) * B_ + b) * H3_ + n * 192;
                float4 kv = *(const float4*)(base + 64 + d4);
                KP[rr * 65 + d4 + 0] = kv.x; KP[rr * 65 + d4 + 1] = kv.y;
                KP[rr * 65 + d4 + 2] = kv.z; KP[rr * 65 + d4 + 3] = kv.w;
                float4 vv = *(const float4*)(base + 128 + d4);
                *(float4*)(Vs + rr * 64 + d4) = vv;
            }
        }
        __syncthreads();
        float sacc[4][4] = {};
#pragma unroll 8
        for (int d = 0; d < 64; ++d) {
            float a[4], kr[4];
#pragma unroll
            for (int i = 0; i < 4; i++) a[i]  = Qs[(ty * 4 + i) * 64 + d];
#pragma unroll
            for (int c = 0; c < 4; c++) kr[c] = KP[(tx * 4 + c) * 65 + d];
#pragma unroll
            for (int i = 0; i < 4; i++)
#pragma unroll
                for (int c = 0; c < 4; c++) sacc[i][c] = fmaf(a[i], kr[c], sacc[i][c]);
        }
        if (j == qt) {
#pragma unroll
            for (int i = 0; i < 4; i++)
#pragma unroll
                for (int c = 0; c < 4; c++)
                    if (tx * 4 + c > ty * 4 + i) sacc[i][c] = -1e30f;
        }
        float mx[4], mnew[4], scl[4], rs[4];
#pragma unroll
        for (int i = 0; i < 4; i++) {
            mx[i] = fmaxf(fmaxf(sacc[i][0], sacc[i][1]), fmaxf(sacc[i][2], sacc[i][3]));
            for (int oo = 8; oo; oo >>= 1)
                mx[i] = fmaxf(mx[i], __shfl_xor_sync(0xffffffffu, mx[i], oo));
            mnew[i] = fmaxf(m_run[i], mx[i]);
            scl[i]  = expf(m_run[i] - mnew[i]);
            m_run[i] = mnew[i];
            rs[i] = 0.f;
#pragma unroll
            for (int c = 0; c < 4; c++) {
                sacc[i][c] = expf(sacc[i][c] - mnew[i]);
                rs[i] += sacc[i][c];
            }
            for (int oo = 8; oo; oo >>= 1)
                rs[i] += __shfl_xor_sync(0xffffffffu, rs[i], oo);
            l_run[i] = l_run[i] * scl[i] + rs[i];
#pragma unroll
            for (int c = 0; c < 4; c++) o[i][c] *= scl[i];
        }
        __syncthreads();
#pragma unroll
        for (int i = 0; i < 4; i++)
#pragma unroll
            for (int c = 0; c < 4; c++)
                KP[(ty * 4 + i) * 65 + tx * 4 + c] = sacc[i][c];
        __syncthreads();
#pragma unroll 8
        for (int d = 0; d < 64; ++d) {
            float pi[4], vj[4];
#pragma unroll
            for (int i = 0; i < 4; i++) pi[i] = KP[(ty * 4 + i) * 65 + d];
#pragma unroll
            for (int c = 0; c < 4; c++) vj[c] = Vs[d * 64 + tx * 4 + c];
#pragma unroll
            for (int i = 0; i < 4; i++)
#pragma unroll
                for (int c = 0; c < 4; c++) o[i][c] = fmaf(pi[i], vj[c], o[i][c]);
        }
    }
#pragma unroll
    for (int i = 0; i < 4; i++) {
        float invl = 1.0f / l_run[i];
#pragma unroll
        for (int c = 0; c < 4; c++)
            g_ctx[((size_t)(q0 + ty * 4 + i) * B_ + b) * H_ + n * HD_ + tx * 4 + c] = o[i][c] * invl;
    }
}

// ======================= gate + routing =======================
__global__ void k_gate(const float* __restrict__ gw) {
    int gidx = blockIdx.x * blockDim.x + threadIdx.x;
    int t = gidx >> 5, lane = gidx & 31;
    if (t >= T_) return;
    const float* x = g_ln2 + (size_t)t * H_;
    float s0 = 0, s1 = 0, s2 = 0, s3 = 0;
    for (int h = lane; h < H_; h += 32) {
        float xv = x[h];
        s0 = fmaf(xv, gw[h],          s0);
        s1 = fmaf(xv, gw[H_ + h],     s1);
        s2 = fmaf(xv, gw[2 * H_ + h], s2);
        s3 = fmaf(xv, gw[3 * H_ + h], s3);
    }
    for (int o = 16; o; o >>= 1) {
        s0 += __shfl_xor_sync(0xffffffffu, s0, o);
        s1 += __shfl_xor_sync(0xffffffffu, s1, o);
        s2 += __shfl_xor_sync(0xffffffffu, s2, o);
        s3 += __shfl_xor_sync(0xffffffffu, s3, o);
    }
    if (lane == 0) {
        float l[4] = {s0, s1, s2, s3};
        float mx = fmaxf(fmaxf(l[0], l[1]), fmaxf(l[2], l[3]));
        float ex[4], z = 0.f;
        for (int e = 0; e < 4; e++) { ex[e] = expf(l[e] - mx); z += ex[e]; }
        int best = 0; float bp = ex[0];
        for (int e = 1; e < 4; e++) if (ex[e] > bp) { bp = ex[e]; best = e; }
        g_eidx[t] = best;
        g_prob[t] = bp / z;
    }
}
__global__ void k_zero()  { if (threadIdx.x < E_) g_cnt[threadIdx.x] = 0; }
__global__ void k_count() { int t = blockIdx.x * 256 + threadIdx.x; if (t < T_) atomicAdd(&g_cnt[g_eidx[t]], 1); }
__global__ void k_offsets() {
    if (threadIdx.x == 0) {
        int a = 0;
        for (int e = 0; e < E_; e++) { g_off[e] = a; g_fill[e] = a; a += g_cnt[e]; }
        g_off[E_] = a;
    }
}
__global__ void k_scatter() {
    int t = blockIdx.x * 256 + threadIdx.x;
    if (t < T_) { int p = atomicAdd(&g_fill[g_eidx[t]], 1); g_perm[p] = t; }
}

// ======================= launch =======================
extern "C" void kernel_launch(void* const* d_in, const int* in_sizes, int n_in,
                              void* d_out, int out_size) {
    const float* hidden = (const float*)d_in[0];
    const float* ln1w = (const float*)d_in[2];
    const float* ln1b = (const float*)d_in[3];
    const float* qkvw = (const float*)d_in[4];
    const float* qkvb = (const float*)d_in[5];
    const float* dw   = (const float*)d_in[6];
    const float* db   = (const float*)d_in[7];
    const float* ln2w = (const float*)d_in[8];
    const float* ln2b = (const float*)d_in[9];
    const float* gw   = (const float*)d_in[10];
    const float* w1   = (const float*)d_in[11];
    const float* b1   = (const float*)d_in[12];
    const float* w2   = (const float*)d_in[13];
    const float* b2   = (const float*)d_in[14];
    float* out = (float*)d_out;

    cudaFuncSetAttribute(k_attn, cudaFuncAttributeMaxDynamicSharedMemorySize, 49408);

    k_ln1<<<T_, 256>>>(hidden, ln1w, ln1b);
    k_tgemm<0, 768, 1><<<dim3(H3_ / 128, T_ / 128), 256>>>(qkvw, qkvb, nullptr, nullptr);
    k_attn<<<dim3(S_ / 64, NH_, B_), dim3(16, 16), 49408>>>();
    k_tgemm<1, 768, 1><<<dim3(H_ / 128, T_ / 128), 256>>>(dw, db, hidden, nullptr);
    k_ln2<<<T_, 256>>>(ln2w, ln2b);
    k_gate<<<T_ / 4, 128>>>(gw);
    k_zero<<<1, 32>>>();
    k_count<<<T_ / 256, 256>>>();
    k_offsets<<<1, 32>>>();
    k_scatter<<<T_ / 256, 256>>>();
    k_tgemm<2, 768, FF_><<<dim3(FF_ / 128, T_ / 128, E_), 256>>>(w1, b1, nullptr, nullptr);
    k_tgemm<3, 3072, H_><<<dim3(H_ / 128, T_ / 128, E_), 256>>>(w2, b2, nullptr, out);
}

// round 8
// speedup vs baseline: 1.9958x; 1.3824x over previous
#include <cuda_runtime.h>
#include <cstdint>
#include <math.h>

#define S_  1024
#define B_  4
#define H_  768
#define NH_ 12
#define HD_ 64
#define FF_ 3072
#define E_  4
#define T_  4096
#define H3_ 2304
#define PITCH 136   // smem row pitch (words): conflict-free for frag loads

// ======================= scratch =======================
__device__ float g_ln1[(size_t)T_ * H_];
__device__ float g_qkv[(size_t)T_ * H3_];
__device__ float g_ctx[(size_t)T_ * H_];
__device__ float g_x1 [(size_t)T_ * H_];
__device__ float g_ln2[(size_t)T_ * H_];
__device__ float g_h1 [(size_t)T_ * FF_];
__device__ int   g_eidx[T_];
__device__ float g_prob[T_];
__device__ int   g_perm[T_];
__device__ int   g_cnt [E_];
__device__ int   g_off [E_ + 1];
__device__ int   g_fill[E_];

// ======================= tf32 helpers =======================
__device__ __forceinline__ uint32_t tf32hi(float x) {
    uint32_t h;
    asm("cvt.rna.tf32.f32 %0, %1;" : "=r"(h) : "f"(x));
    return h;
}
#define MMAT(d, a, b) \
    asm volatile("mma.sync.aligned.m16n8k8.row.col.f32.tf32.tf32.f32 " \
        "{%0,%1,%2,%3}, {%4,%5,%6,%7}, {%8,%9}, {%0,%1,%2,%3};" \
        : "+f"((d)[0]), "+f"((d)[1]), "+f"((d)[2]), "+f"((d)[3]) \
        : "r"((a)[0]), "r"((a)[1]), "r"((a)[2]), "r"((a)[3]), "r"((b)[0]), "r"((b)[1]))

// ======================= layernorm =======================
__device__ __forceinline__ void ln_row(const float* __restrict__ x, float* __restrict__ y,
                                       const float* __restrict__ w, const float* __restrict__ b) {
    __shared__ float red[2][8];
    int tid = threadIdx.x;
    float v0 = x[tid], v1 = x[tid + 256], v2 = x[tid + 512];
    float s  = v0 + v1 + v2;
    float ss = v0 * v0 + v1 * v1 + v2 * v2;
    for (int o = 16; o; o >>= 1) {
        s  += __shfl_xor_sync(0xffffffffu, s,  o);
        ss += __shfl_xor_sync(0xffffffffu, ss, o);
    }
    if ((tid & 31) == 0) { red[0][tid >> 5] = s; red[1][tid >> 5] = ss; }
    __syncthreads();
    if (tid < 32) {
        float a = (tid < 8) ? red[0][tid] : 0.f;
        float c = (tid < 8) ? red[1][tid] : 0.f;
        for (int o = 4; o; o >>= 1) {
            a += __shfl_xor_sync(0xffffffffu, a, o);
            c += __shfl_xor_sync(0xffffffffu, c, o);
        }
        if (tid == 0) { red[0][0] = a; red[1][0] = c; }
    }
    __syncthreads();
    float mean = red[0][0] * (1.0f / H_);
    float var  = red[1][0] * (1.0f / H_) - mean * mean;
    float inv  = rsqrtf(var + 1e-5f);
    y[tid]       = (v0 - mean) * inv * w[tid]       + b[tid];
    y[tid + 256] = (v1 - mean) * inv * w[tid + 256] + b[tid + 256];
    y[tid + 512] = (v2 - mean) * inv * w[tid + 512] + b[tid + 512];
}

__global__ void k_ln1(const float* __restrict__ hidden,
                      const float* __restrict__ w, const float* __restrict__ b) {
    ln_row(hidden + (size_t)blockIdx.x * H_, g_ln1 + (size_t)blockIdx.x * H_, w, b);
}
__global__ void k_ln2(const float* __restrict__ w, const float* __restrict__ b) {
    ln_row(g_x1 + (size_t)blockIdx.x * H_, g_ln2 + (size_t)blockIdx.x * H_, w, b);
}

// ======================= TF32 tensor-core GEMM (split hoisted to smem) ==========
// 128x128 CTA tile, 8 warps (2x4), warp tile 64x32, BK=16 (2x k8 mma steps).
// smem holds tf32 hi (+ lo when NT==3), split ONCE at store time.
// NT==3: D += Ahi*Bhi + Ahi*Blo + Alo*Bhi (err ~2^-21) -- QKV/dense (routing-critical)
// NT==1: D += Ahi*Bhi (err ~2^-11) -- MoE GEMMs (post-routing; 1e-3 rel -> ~1e-4 output)
// A [M][K] row-major (MODE 2 gathered rows, MODE 3 compact rows).
// MODE 0/1: B = W[N][K] (transposed store).  MODE 2/3: B = W[K][N] (direct).
template<int MODE, int KDIM, int NSTR, int NT>
__global__ void __launch_bounds__(256) k_tgemm(const float* __restrict__ Bsrc,
                                               const float* __restrict__ bias,
                                               const float* __restrict__ extra,
                                               float* __restrict__ outp) {
    constexpr bool TRB = (MODE < 2);
    constexpr int LOSZ = (NT == 3) ? 16 * PITCH : 1;
    __shared__ uint32_t Ash[16 * PITCH], Bsh[16 * PITCH];
    __shared__ uint32_t Asl[LOSZ], Bsl[LOSZ];
    __shared__ int sridx[128];

    const int tid = threadIdx.x;
    const int n0 = blockIdx.x * 128;
    const int m0 = blockIdx.y * 128;
    const int e  = (MODE >= 2) ? blockIdx.z : 0;

    int beg = 0, cnt = T_;
    if (MODE >= 2) {
        beg = g_off[e]; cnt = g_off[e + 1] - beg;
        if (m0 >= cnt) return;
    }

    const float* Abase = (MODE == 0) ? g_ln1 : (MODE == 1) ? g_ctx
                        : (MODE == 2) ? g_ln2 : g_h1;
    const float* Bbase = Bsrc;
    if (MODE == 2) Bbase += (size_t)e * H_ * FF_;
    if (MODE == 3) Bbase += (size_t)e * FF_ * H_;

    if (MODE >= 2 && tid < 128)
        sridx[tid] = (m0 + tid < cnt) ? g_perm[beg + m0 + tid] : -1;
    if (MODE >= 2) __syncthreads();

    // ---- loaders (structure identical to proven R6/R7 kernels) ----
    const int ar = tid >> 2;          // 0..63
    const int ac = tid & 3;           // 0..3
    const int arows[2] = { ar, ar + 64 };
    const float* pA[2];
    bool avA[2];
#pragma unroll
    for (int i = 0; i < 2; i++) {
        int r = arows[i];
        long grow = m0 + r;
        avA[i] = true;
        if (MODE == 2) { int t = sridx[r]; avA[i] = (t >= 0); grow = avA[i] ? t : 0; }
        if (MODE == 3) { avA[i] = (m0 + r < cnt); grow = avA[i] ? (beg + m0 + r) : 0; }
        pA[i] = Abase + (size_t)grow * KDIM + ac * 4;
    }
    const float* pB[2];             // TRB
    const float* pBn = nullptr;     // !TRB
    const int bk = tid >> 4;        // 0..15
    const int bc = tid & 15;        // 0..15
    if (TRB) {
#pragma unroll
        for (int i = 0; i < 2; i++)
            pB[i] = Bbase + (size_t)(n0 + arows[i]) * KDIM + ac * 4;
    } else {
        pBn = Bbase + (size_t)bk * NSTR + n0 + bc * 4;
    }

    float4 ra[2], rb[2];
    const float4 fz = make_float4(0.f, 0.f, 0.f, 0.f);

    // ---- split+store helpers ----
    auto storeA = [&](int i) {
        const float* v = (const float*)&ra[i];
#pragma unroll
        for (int j = 0; j < 4; j++) {
            uint32_t h = tf32hi(v[j]);
            Ash[(ac * 4 + j) * PITCH + arows[i]] = h;
            if (NT == 3)
                Asl[(ac * 4 + j) * PITCH + arows[i]] = tf32hi(v[j] - __uint_as_float(h));
        }
    };
    auto storeB = [&]() {
        if (TRB) {
#pragma unroll
            for (int i = 0; i < 2; i++) {
                const float* v = (const float*)&rb[i];
#pragma unroll
                for (int j = 0; j < 4; j++) {
                    uint32_t h = tf32hi(v[j]);
                    Bsh[(ac * 4 + j) * PITCH + arows[i]] = h;
                    if (NT == 3)
                        Bsl[(ac * 4 + j) * PITCH + arows[i]] = tf32hi(v[j] - __uint_as_float(h));
                }
            }
        } else {
#pragma unroll
            for (int i = 0; i < 2; i++) {
                const float* v = (const float*)&rb[i];
#pragma unroll
                for (int j = 0; j < 4; j++) {
                    uint32_t h = tf32hi(v[j]);
                    Bsh[bk * PITCH + bc * 4 + i * 64 + j] = h;
                    if (NT == 3)
                        Bsl[bk * PITCH + bc * 4 + i * 64 + j] = tf32hi(v[j] - __uint_as_float(h));
                }
            }
        }
    };

    // initial load k0=0
#pragma unroll
    for (int i = 0; i < 2; i++) {
        ra[i] = avA[i] ? *(const float4*)(pA[i]) : fz;
        if (TRB) rb[i] = *(const float4*)(pB[i]);
    }
    if (!TRB) {
        rb[0] = *(const float4*)(pBn);
        rb[1] = *(const float4*)(pBn + 64);
    }
    storeA(0); storeA(1); storeB();
    __syncthreads();

    // ---- fragment coords ----
    const int wid = tid >> 5, lane = tid & 31;
    const int wm = wid >> 2, wn = wid & 3;   // warp tile (wm*64, wn*32)
    const int fr = lane >> 2;                // 0..7
    const int fc = lane & 3;                 // 0..3

    float acc[4][4][4] = {};

    for (int k0 = 0; k0 < KDIM; k0 += 16) {
        const bool more = (k0 + 16) < KDIM;
        if (more) {
            int kn = k0 + 16;
#pragma unroll
            for (int i = 0; i < 2; i++) {
                ra[i] = avA[i] ? *(const float4*)(pA[i] + kn) : fz;
                if (TRB) rb[i] = *(const float4*)(pB[i] + kn);
            }
            if (!TRB) {
                rb[0] = *(const float4*)(pBn + (size_t)kn * NSTR);
                rb[1] = *(const float4*)(pBn + (size_t)kn * NSTR + 64);
            }
        }
        // ---- compute: 2 x k8 mma steps ----
#pragma unroll
        for (int ks = 0; ks < 2; ks++) {
            const int kofs = ks * 8;
            uint32_t ahi[4][4], alo[4][4];
#pragma unroll
            for (int mi = 0; mi < 4; mi++) {
                const int mb = wm * 64 + mi * 16 + fr;
                ahi[mi][0] = Ash[(kofs + fc    ) * PITCH + mb    ];
                ahi[mi][1] = Ash[(kofs + fc    ) * PITCH + mb + 8];
                ahi[mi][2] = Ash[(kofs + fc + 4) * PITCH + mb    ];
                ahi[mi][3] = Ash[(kofs + fc + 4) * PITCH + mb + 8];
                if (NT == 3) {
                    alo[mi][0] = Asl[(kofs + fc    ) * PITCH + mb    ];
                    alo[mi][1] = Asl[(kofs + fc    ) * PITCH + mb + 8];
                    alo[mi][2] = Asl[(kofs + fc + 4) * PITCH + mb    ];
                    alo[mi][3] = Asl[(kofs + fc + 4) * PITCH + mb + 8];
                }
            }
#pragma unroll
            for (int ni = 0; ni < 4; ni++) {
                const int nb = wn * 32 + ni * 8 + fr;
                uint32_t bhi[2], blo[2];
                bhi[0] = Bsh[(kofs + fc    ) * PITCH + nb];
                bhi[1] = Bsh[(kofs + fc + 4) * PITCH + nb];
                if (NT == 3) {
                    blo[0] = Bsl[(kofs + fc    ) * PITCH + nb];
                    blo[1] = Bsl[(kofs + fc + 4) * PITCH + nb];
                }
#pragma unroll
                for (int mi = 0; mi < 4; mi++) {
                    MMAT(acc[mi][ni], ahi[mi], bhi);
                    if (NT == 3) {
                        MMAT(acc[mi][ni], ahi[mi], blo);
                        MMAT(acc[mi][ni], alo[mi], bhi);
                    }
                }
            }
        }
        if (more) {
            __syncthreads();
            storeA(0); storeA(1); storeB();
            __syncthreads();
        }
    }

    // ---- epilogue: C frag rows lane>>2 (+8), cols 2*(lane&3) (+1) ----
#pragma unroll
    for (int mi = 0; mi < 4; mi++) {
#pragma unroll
        for (int half = 0; half < 2; half++) {
            const int rl = wm * 64 + mi * 16 + fr + half * 8;
            bool valid = true;
            int tkn = 0; float pgate = 0.f;
            if (MODE == 2) valid = (m0 + rl) < cnt;
            if (MODE == 3) { tkn = sridx[rl]; valid = (tkn >= 0); if (valid) pgate = g_prob[tkn]; }
            if (!valid) continue;
#pragma unroll
            for (int ni = 0; ni < 4; ni++) {
                const int n = n0 + wn * 32 + ni * 8 + fc * 2;
                const float v0 = acc[mi][ni][half * 2 + 0];
                const float v1 = acc[mi][ni][half * 2 + 1];
                if (MODE == 0) {
                    size_t o = (size_t)(m0 + rl) * H3_ + n;
                    g_qkv[o]     = v0 + bias[n];
                    g_qkv[o + 1] = v1 + bias[n + 1];
                } else if (MODE == 1) {
                    size_t o = (size_t)(m0 + rl) * H_ + n;
                    g_x1[o]     = extra[o]     + v0 + bias[n];
                    g_x1[o + 1] = extra[o + 1] + v1 + bias[n + 1];
                } else if (MODE == 2) {
                    size_t o = (size_t)(beg + m0 + rl) * FF_ + n;
                    float x0 = v0 + bias[(size_t)e * FF_ + n];
                    float x1 = v1 + bias[(size_t)e * FF_ + n + 1];
                    g_h1[o]     = 0.5f * x0 * (1.0f + erff(x0 * 0.70710678118654752f));
                    g_h1[o + 1] = 0.5f * x1 * (1.0f + erff(x1 * 0.70710678118654752f));
                } else {
                    size_t o = (size_t)tkn * H_ + n;
                    outp[o]     = g_x1[o]     + pgate * (v0 + bias[(size_t)e * H_ + n]);
                    outp[o + 1] = g_x1[o + 1] + pgate * (v1 + bias[(size_t)e * H_ + n + 1]);
                }
            }
        }
    }
}

// ======================= causal flash attention (SIMT fp32, proven) =======================
__global__ void k_attn() {
    extern __shared__ float sm[];
    float* Qs = sm;
    float* KP = sm + 4096;
    float* Vs = sm + 4096 + 4160;
    int qt = blockIdx.x, n = blockIdx.y, b = blockIdx.z;
    int tx = threadIdx.x, ty = threadIdx.y, tid = ty * 16 + tx;
    int q0 = qt * 64;
    const float SCALE = 0.125f;
    {
        int r = tid >> 4, d4 = (tid & 15) * 4;
        for (int rr = r; rr < 64; rr += 16) {
            float4 v = *(const float4*)(g_qkv + ((size_t)(q0 + rr) * B_ + b) * H3_ + n * 192 + d4);
            float* dst = Qs + rr * 64 + d4;
            dst[0] = v.x * SCALE; dst[1] = v.y * SCALE; dst[2] = v.z * SCALE; dst[3] = v.w * SCALE;
        }
    }
    float o[4][4] = {};
    float m_run[4] = {-1e30f, -1e30f, -1e30f, -1e30f};
    float l_run[4] = {0.f, 0.f, 0.f, 0.f};

    for (int j = 0; j <= qt; ++j) {
        __syncthreads();
        int k0 = j * 64;
        {
            int r = tid >> 4, d4 = (tid & 15) * 4;
            for (int rr = r; rr < 64; rr += 16) {
                const float* base = g_qkv + ((size_t)(k0 + rr) * B_ + b) * H3_ + n * 192;
                float4 kv = *(const float4*)(base + 64 + d4);
                KP[rr * 65 + d4 + 0] = kv.x; KP[rr * 65 + d4 + 1] = kv.y;
                KP[rr * 65 + d4 + 2] = kv.z; KP[rr * 65 + d4 + 3] = kv.w;
                float4 vv = *(const float4*)(base + 128 + d4);
                *(float4*)(Vs + rr * 64 + d4) = vv;
            }
        }
        __syncthreads();
        float sacc[4][4] = {};
#pragma unroll 8
        for (int d = 0; d < 64; ++d) {
            float a[4], kr[4];
#pragma unroll
            for (int i = 0; i < 4; i++) a[i]  = Qs[(ty * 4 + i) * 64 + d];
#pragma unroll
            for (int c = 0; c < 4; c++) kr[c] = KP[(tx * 4 + c) * 65 + d];
#pragma unroll
            for (int i = 0; i < 4; i++)
#pragma unroll
                for (int c = 0; c < 4; c++) sacc[i][c] = fmaf(a[i], kr[c], sacc[i][c]);
        }
        if (j == qt) {
#pragma unroll
            for (int i = 0; i < 4; i++)
#pragma unroll
                for (int c = 0; c < 4; c++)
                    if (tx * 4 + c > ty * 4 + i) sacc[i][c] = -1e30f;
        }
        float mx[4], mnew[4], scl[4], rs[4];
#pragma unroll
        for (int i = 0; i < 4; i++) {
            mx[i] = fmaxf(fmaxf(sacc[i][0], sacc[i][1]), fmaxf(sacc[i][2], sacc[i][3]));
            for (int oo = 8; oo; oo >>= 1)
                mx[i] = fmaxf(mx[i], __shfl_xor_sync(0xffffffffu, mx[i], oo));
            mnew[i] = fmaxf(m_run[i], mx[i]);
            scl[i]  = expf(m_run[i] - mnew[i]);
            m_run[i] = mnew[i];
            rs[i] = 0.f;
#pragma unroll
            for (int c = 0; c < 4; c++) {
                sacc[i][c] = expf(sacc[i][c] - mnew[i]);
                rs[i] += sacc[i][c];
            }
            for (int oo = 8; oo; oo >>= 1)
                rs[i] += __shfl_xor_sync(0xffffffffu, rs[i], oo);
            l_run[i] = l_run[i] * scl[i] + rs[i];
#pragma unroll
            for (int c = 0; c < 4; c++) o[i][c] *= scl[i];
        }
        __syncthreads();
#pragma unroll
        for (int i = 0; i < 4; i++)
#pragma unroll
            for (int c = 0; c < 4; c++)
                KP[(ty * 4 + i) * 65 + tx * 4 + c] = sacc[i][c];
        __syncthreads();
#pragma unroll 8
        for (int d = 0; d < 64; ++d) {
            float pi[4], vj[4];
#pragma unroll
            for (int i = 0; i < 4; i++) pi[i] = KP[(ty * 4 + i) * 65 + d];
#pragma unroll
            for (int c = 0; c < 4; c++) vj[c] = Vs[d * 64 + tx * 4 + c];
#pragma unroll
            for (int i = 0; i < 4; i++)
#pragma unroll
                for (int c = 0; c < 4; c++) o[i][c] = fmaf(pi[i], vj[c], o[i][c]);
        }
    }
#pragma unroll
    for (int i = 0; i < 4; i++) {
        float invl = 1.0f / l_run[i];
#pragma unroll
        for (int c = 0; c < 4; c++)
            g_ctx[((size_t)(q0 + ty * 4 + i) * B_ + b) * H_ + n * HD_ + tx * 4 + c] = o[i][c] * invl;
    }
}

// ======================= gate + routing =======================
__global__ void k_gate(const float* __restrict__ gw) {
    int gidx = blockIdx.x * blockDim.x + threadIdx.x;
    int t = gidx >> 5, lane = gidx & 31;
    if (t >= T_) return;
    const float* x = g_ln2 + (size_t)t * H_;
    float s0 = 0, s1 = 0, s2 = 0, s3 = 0;
    for (int h = lane; h < H_; h += 32) {
        float xv = x[h];
        s0 = fmaf(xv, gw[h],          s0);
        s1 = fmaf(xv, gw[H_ + h],     s1);
        s2 = fmaf(xv, gw[2 * H_ + h], s2);
        s3 = fmaf(xv, gw[3 * H_ + h], s3);
    }
    for (int o = 16; o; o >>= 1) {
        s0 += __shfl_xor_sync(0xffffffffu, s0, o);
        s1 += __shfl_xor_sync(0xffffffffu, s1, o);
        s2 += __shfl_xor_sync(0xffffffffu, s2, o);
        s3 += __shfl_xor_sync(0xffffffffu, s3, o);
    }
    if (lane == 0) {
        float l[4] = {s0, s1, s2, s3};
        float mx = fmaxf(fmaxf(l[0], l[1]), fmaxf(l[2], l[3]));
        float ex[4], z = 0.f;
        for (int e = 0; e < 4; e++) { ex[e] = expf(l[e] - mx); z += ex[e]; }
        int best = 0; float bp = ex[0];
        for (int e = 1; e < 4; e++) if (ex[e] > bp) { bp = ex[e]; best = e; }
        g_eidx[t] = best;
        g_prob[t] = bp / z;
    }
}
__global__ void k_zero()  { if (threadIdx.x < E_) g_cnt[threadIdx.x] = 0; }
__global__ void k_count() { int t = blockIdx.x * 256 + threadIdx.x; if (t < T_) atomicAdd(&g_cnt[g_eidx[t]], 1); }
__global__ void k_offsets() {
    if (threadIdx.x == 0) {
        int a = 0;
        for (int e = 0; e < E_; e++) { g_off[e] = a; g_fill[e] = a; a += g_cnt[e]; }
        g_off[E_] = a;
    }
}
__global__ void k_scatter() {
    int t = blockIdx.x * 256 + threadIdx.x;
    if (t < T_) { int p = atomicAdd(&g_fill[g_eidx[t]], 1); g_perm[p] = t; }
}

// ======================= launch =======================
extern "C" void kernel_launch(void* const* d_in, const int* in_sizes, int n_in,
                              void* d_out, int out_size) {
    const float* hidden = (const float*)d_in[0];
    const float* ln1w = (const float*)d_in[2];
    const float* ln1b = (const float*)d_in[3];
    const float* qkvw = (const float*)d_in[4];
    const float* qkvb = (const float*)d_in[5];
    const float* dw   = (const float*)d_in[6];
    const float* db   = (const float*)d_in[7];
    const float* ln2w = (const float*)d_in[8];
    const float* ln2b = (const float*)d_in[9];
    const float* gw   = (const float*)d_in[10];
    const float* w1   = (const float*)d_in[11];
    const float* b1   = (const float*)d_in[12];
    const float* w2   = (const float*)d_in[13];
    const float* b2   = (const float*)d_in[14];
    float* out = (float*)d_out;

    cudaFuncSetAttribute(k_attn, cudaFuncAttributeMaxDynamicSharedMemorySize, 49408);

    k_ln1<<<T_, 256>>>(hidden, ln1w, ln1b);
    k_tgemm<0, 768, 1, 3><<<dim3(H3_ / 128, T_ / 128), 256>>>(qkvw, qkvb, nullptr, nullptr);
    k_attn<<<dim3(S_ / 64, NH_, B_), dim3(16, 16), 49408>>>();
    k_tgemm<1, 768, 1, 3><<<dim3(H_ / 128, T_ / 128), 256>>>(dw, db, hidden, nullptr);
    k_ln2<<<T_, 256>>>(ln2w, ln2b);
    k_gate<<<T_ / 4, 128>>>(gw);
    k_zero<<<1, 32>>>();
    k_count<<<T_ / 256, 256>>>();
    k_offsets<<<1, 32>>>();
    k_scatter<<<T_ / 256, 256>>>();
    k_tgemm<2, 768, FF_, 1><<<dim3(FF_ / 128, T_ / 128, E_), 256>>>(w1, b1, nullptr, nullptr);
    k_tgemm<3, 3072, H_, 1><<<dim3(H_ / 128, T_ / 128, E_), 256>>>(w2, b2, nullptr, out);
}

// round 9
// speedup vs baseline: 2.0827x; 1.0436x over previous
#include <cuda_runtime.h>
#include <cstdint>
#include <math.h>

#define S_  1024
#define B_  4
#define H_  768
#define NH_ 12
#define HD_ 64
#define FF_ 3072
#define E_  4
#define T_  4096
#define H3_ 2304
#define PITCH 136           // smem row pitch (words): conflict-free for frag loads
#define SLAB  (16 * PITCH)  // words per operand slab buffer

// ======================= scratch =======================
__device__ float g_ln1[(size_t)T_ * H_];
__device__ float g_qkv[(size_t)T_ * H3_];
__device__ float g_ctx[(size_t)T_ * H_];
__device__ float g_x1 [(size_t)T_ * H_];
__device__ float g_ln2[(size_t)T_ * H_];
__device__ float g_h1 [(size_t)T_ * FF_];
__device__ int   g_eidx[T_];
__device__ float g_prob[T_];
__device__ int   g_perm[T_];
__device__ int   g_cnt [E_];
__device__ int   g_off [E_ + 1];
__device__ int   g_fill[E_];

// ======================= tf32 helpers =======================
__device__ __forceinline__ uint32_t tf32hi(float x) {
    uint32_t h;
    asm("cvt.rna.tf32.f32 %0, %1;" : "=r"(h) : "f"(x));
    return h;
}
#define MMAT(d, a, b) \
    asm volatile("mma.sync.aligned.m16n8k8.row.col.f32.tf32.tf32.f32 " \
        "{%0,%1,%2,%3}, {%4,%5,%6,%7}, {%8,%9}, {%0,%1,%2,%3};" \
        : "+f"((d)[0]), "+f"((d)[1]), "+f"((d)[2]), "+f"((d)[3]) \
        : "r"((a)[0]), "r"((a)[1]), "r"((a)[2]), "r"((a)[3]), "r"((b)[0]), "r"((b)[1]))

// ======================= layernorm =======================
__device__ __forceinline__ void ln_row(const float* __restrict__ x, float* __restrict__ y,
                                       const float* __restrict__ w, const float* __restrict__ b) {
    __shared__ float red[2][8];
    int tid = threadIdx.x;
    float v0 = x[tid], v1 = x[tid + 256], v2 = x[tid + 512];
    float s  = v0 + v1 + v2;
    float ss = v0 * v0 + v1 * v1 + v2 * v2;
    for (int o = 16; o; o >>= 1) {
        s  += __shfl_xor_sync(0xffffffffu, s,  o);
        ss += __shfl_xor_sync(0xffffffffu, ss, o);
    }
    if ((tid & 31) == 0) { red[0][tid >> 5] = s; red[1][tid >> 5] = ss; }
    __syncthreads();
    if (tid < 32) {
        float a = (tid < 8) ? red[0][tid] : 0.f;
        float c = (tid < 8) ? red[1][tid] : 0.f;
        for (int o = 4; o; o >>= 1) {
            a += __shfl_xor_sync(0xffffffffu, a, o);
            c += __shfl_xor_sync(0xffffffffu, c, o);
        }
        if (tid == 0) { red[0][0] = a; red[1][0] = c; }
    }
    __syncthreads();
    float mean = red[0][0] * (1.0f / H_);
    float var  = red[1][0] * (1.0f / H_) - mean * mean;
    float inv  = rsqrtf(var + 1e-5f);
    y[tid]       = (v0 - mean) * inv * w[tid]       + b[tid];
    y[tid + 256] = (v1 - mean) * inv * w[tid + 256] + b[tid + 256];
    y[tid + 512] = (v2 - mean) * inv * w[tid + 512] + b[tid + 512];
}

__global__ void k_ln1(const float* __restrict__ hidden,
                      const float* __restrict__ w, const float* __restrict__ b) {
    ln_row(hidden + (size_t)blockIdx.x * H_, g_ln1 + (size_t)blockIdx.x * H_, w, b);
}
__global__ void k_ln2(const float* __restrict__ w, const float* __restrict__ b) {
    ln_row(g_x1 + (size_t)blockIdx.x * H_, g_ln2 + (size_t)blockIdx.x * H_, w, b);
}

// ======================= TF32 tensor-core GEMM (double-buffered pipeline) ==========
// 128x128 CTA tile, 8 warps (2x4), warp tile 64x32, BK=16 (2x k8 mma steps).
// Dynamic smem: 2 slab buffers per operand; tf32 split hoisted to store time.
// NT==3: D += Ahi*Bhi + Ahi*Blo + Alo*Bhi (QKV/dense, routing-critical)
// NT==1: D += Ahi*Bhi (MoE, post-routing)
// MODE 0/1: B = W[N][K] (transposed store).  MODE 2/3: B = W[K][N] (direct).
template<int MODE, int KDIM, int NSTR, int NT>
__global__ void __launch_bounds__(256) k_tgemm(const float* __restrict__ Bsrc,
                                               const float* __restrict__ bias,
                                               const float* __restrict__ extra,
                                               float* __restrict__ outp) {
    constexpr bool TRB = (MODE < 2);
    extern __shared__ uint32_t dsm[];
    uint32_t* Ash = dsm;                                    // [2][SLAB]
    uint32_t* Bsh = dsm + 2 * SLAB;                         // [2][SLAB]
    uint32_t* Asl = (NT == 3) ? dsm + 4 * SLAB : dsm;       // [2][SLAB] (NT==3)
    uint32_t* Bsl = (NT == 3) ? dsm + 6 * SLAB : dsm;
    int* sridx = (int*)(dsm + ((NT == 3) ? 8 : 4) * SLAB);  // [128]

    const int tid = threadIdx.x;
    const int n0 = blockIdx.x * 128;
    const int m0 = blockIdx.y * 128;
    const int e  = (MODE >= 2) ? blockIdx.z : 0;

    int beg = 0, cnt = T_;
    if (MODE >= 2) {
        beg = g_off[e]; cnt = g_off[e + 1] - beg;
        if (m0 >= cnt) return;
    }

    const float* Abase = (MODE == 0) ? g_ln1 : (MODE == 1) ? g_ctx
                        : (MODE == 2) ? g_ln2 : g_h1;
    const float* Bbase = Bsrc;
    if (MODE == 2) Bbase += (size_t)e * H_ * FF_;
    if (MODE == 3) Bbase += (size_t)e * FF_ * H_;

    if (MODE >= 2 && tid < 128)
        sridx[tid] = (m0 + tid < cnt) ? g_perm[beg + m0 + tid] : -1;
    if (MODE >= 2) __syncthreads();

    // ---- loaders ----
    const int ar = tid >> 2;          // 0..63
    const int ac = tid & 3;           // 0..3
    const int arows[2] = { ar, ar + 64 };
    const float* pA[2];
    bool avA[2];
#pragma unroll
    for (int i = 0; i < 2; i++) {
        int r = arows[i];
        long grow = m0 + r;
        avA[i] = true;
        if (MODE == 2) { int t = sridx[r]; avA[i] = (t >= 0); grow = avA[i] ? t : 0; }
        if (MODE == 3) { avA[i] = (m0 + r < cnt); grow = avA[i] ? (beg + m0 + r) : 0; }
        pA[i] = Abase + (size_t)grow * KDIM + ac * 4;
    }
    const float* pB[2];             // TRB
    const float* pBn = nullptr;     // !TRB
    const int bk = tid >> 4;        // 0..15
    const int bc = tid & 15;        // 0..15
    if (TRB) {
#pragma unroll
        for (int i = 0; i < 2; i++)
            pB[i] = Bbase + (size_t)(n0 + arows[i]) * KDIM + ac * 4;
    } else {
        pBn = Bbase + (size_t)bk * NSTR + n0 + bc * 4;
    }

    float4 ra[2], rb[2];
    const float4 fz = make_float4(0.f, 0.f, 0.f, 0.f);

    // ---- split+store helpers (into buffer `buf`) ----
    auto storeA = [&](int i, int buf) {
        const float* v = (const float*)&ra[i];
        uint32_t* dsth = Ash + buf * SLAB;
        uint32_t* dstl = Asl + buf * SLAB;
#pragma unroll
        for (int j = 0; j < 4; j++) {
            uint32_t h = tf32hi(v[j]);
            dsth[(ac * 4 + j) * PITCH + arows[i]] = h;
            if (NT == 3)
                dstl[(ac * 4 + j) * PITCH + arows[i]] = tf32hi(v[j] - __uint_as_float(h));
        }
    };
    auto storeB = [&](int buf) {
        uint32_t* dsth = Bsh + buf * SLAB;
        uint32_t* dstl = Bsl + buf * SLAB;
        if (TRB) {
#pragma unroll
            for (int i = 0; i < 2; i++) {
                const float* v = (const float*)&rb[i];
#pragma unroll
                for (int j = 0; j < 4; j++) {
                    uint32_t h = tf32hi(v[j]);
                    dsth[(ac * 4 + j) * PITCH + arows[i]] = h;
                    if (NT == 3)
                        dstl[(ac * 4 + j) * PITCH + arows[i]] = tf32hi(v[j] - __uint_as_float(h));
                }
            }
        } else {
#pragma unroll
            for (int i = 0; i < 2; i++) {
                const float* v = (const float*)&rb[i];
#pragma unroll
                for (int j = 0; j < 4; j++) {
                    uint32_t h = tf32hi(v[j]);
                    dsth[bk * PITCH + bc * 4 + i * 64 + j] = h;
                    if (NT == 3)
                        dstl[bk * PITCH + bc * 4 + i * 64 + j] = tf32hi(v[j] - __uint_as_float(h));
                }
            }
        }
    };
    auto loadSlab = [&](int kn) {
#pragma unroll
        for (int i = 0; i < 2; i++) {
            ra[i] = avA[i] ? *(const float4*)(pA[i] + kn) : fz;
            if (TRB) rb[i] = *(const float4*)(pB[i] + kn);
        }
        if (!TRB) {
            rb[0] = *(const float4*)(pBn + (size_t)kn * NSTR);
            rb[1] = *(const float4*)(pBn + (size_t)kn * NSTR + 64);
        }
    };

    // initial: slab 0 -> buf 0
    loadSlab(0);
    storeA(0, 0); storeA(1, 0); storeB(0);
    __syncthreads();

    // ---- fragment coords ----
    const int wid = tid >> 5, lane = tid & 31;
    const int wm = wid >> 2, wn = wid & 3;   // warp tile (wm*64, wn*32)
    const int fr = lane >> 2;                // 0..7
    const int fc = lane & 3;                 // 0..3

    float acc[4][4][4] = {};
    int cur = 0;

    for (int k0 = 0; k0 < KDIM; k0 += 16) {
        const bool more = (k0 + 16) < KDIM;
        if (more) loadSlab(k0 + 16);

        const uint32_t* ah_ = Ash + cur * SLAB;
        const uint32_t* al_ = Asl + cur * SLAB;
        const uint32_t* bh_ = Bsh + cur * SLAB;
        const uint32_t* bl_ = Bsl + cur * SLAB;
#pragma unroll
        for (int ks = 0; ks < 2; ks++) {
            const int kofs = ks * 8;
            uint32_t ahi[4][4], alo[4][4];
#pragma unroll
            for (int mi = 0; mi < 4; mi++) {
                const int mb = wm * 64 + mi * 16 + fr;
                ahi[mi][0] = ah_[(kofs + fc    ) * PITCH + mb    ];
                ahi[mi][1] = ah_[(kofs + fc    ) * PITCH + mb + 8];
                ahi[mi][2] = ah_[(kofs + fc + 4) * PITCH + mb    ];
                ahi[mi][3] = ah_[(kofs + fc + 4) * PITCH + mb + 8];
                if (NT == 3) {
                    alo[mi][0] = al_[(kofs + fc    ) * PITCH + mb    ];
                    alo[mi][1] = al_[(kofs + fc    ) * PITCH + mb + 8];
                    alo[mi][2] = al_[(kofs + fc + 4) * PITCH + mb    ];
                    alo[mi][3] = al_[(kofs + fc + 4) * PITCH + mb + 8];
                }
            }
#pragma unroll
            for (int ni = 0; ni < 4; ni++) {
                const int nb = wn * 32 + ni * 8 + fr;
                uint32_t bhi[2], blo[2];
                bhi[0] = bh_[(kofs + fc    ) * PITCH + nb];
                bhi[1] = bh_[(kofs + fc + 4) * PITCH + nb];
                if (NT == 3) {
                    blo[0] = bl_[(kofs + fc    ) * PITCH + nb];
                    blo[1] = bl_[(kofs + fc + 4) * PITCH + nb];
                }
#pragma unroll
                for (int mi = 0; mi < 4; mi++) {
                    MMAT(acc[mi][ni], ahi[mi], bhi);
                    if (NT == 3) {
                        MMAT(acc[mi][ni], ahi[mi], blo);
                        MMAT(acc[mi][ni], alo[mi], bhi);
                    }
                }
            }
        }
        if (more) {
            storeA(0, cur ^ 1); storeA(1, cur ^ 1); storeB(cur ^ 1);
            __syncthreads();
            cur ^= 1;
        }
    }

    // ---- epilogue ----
#pragma unroll
    for (int mi = 0; mi < 4; mi++) {
#pragma unroll
        for (int half = 0; half < 2; half++) {
            const int rl = wm * 64 + mi * 16 + fr + half * 8;
            bool valid = true;
            int tkn = 0; float pgate = 0.f;
            if (MODE == 2) valid = (m0 + rl) < cnt;
            if (MODE == 3) { tkn = sridx[rl]; valid = (tkn >= 0); if (valid) pgate = g_prob[tkn]; }
            if (!valid) continue;
#pragma unroll
            for (int ni = 0; ni < 4; ni++) {
                const int n = n0 + wn * 32 + ni * 8 + fc * 2;
                const float v0 = acc[mi][ni][half * 2 + 0];
                const float v1 = acc[mi][ni][half * 2 + 1];
                if (MODE == 0) {
                    size_t o = (size_t)(m0 + rl) * H3_ + n;
                    g_qkv[o]     = v0 + bias[n];
                    g_qkv[o + 1] = v1 + bias[n + 1];
                } else if (MODE == 1) {
                    size_t o = (size_t)(m0 + rl) * H_ + n;
                    g_x1[o]     = extra[o]     + v0 + bias[n];
                    g_x1[o + 1] = extra[o + 1] + v1 + bias[n + 1];
                } else if (MODE == 2) {
                    size_t o = (size_t)(beg + m0 + rl) * FF_ + n;
                    float x0 = v0 + bias[(size_t)e * FF_ + n];
                    float x1 = v1 + bias[(size_t)e * FF_ + n + 1];
                    g_h1[o]     = 0.5f * x0 * (1.0f + erff(x0 * 0.70710678118654752f));
                    g_h1[o + 1] = 0.5f * x1 * (1.0f + erff(x1 * 0.70710678118654752f));
                } else {
                    size_t o = (size_t)tkn * H_ + n;
                    outp[o]     = g_x1[o]     + pgate * (v0 + bias[(size_t)e * H_ + n]);
                    outp[o + 1] = g_x1[o + 1] + pgate * (v1 + bias[(size_t)e * H_ + n + 1]);
                }
            }
        }
    }
}

// smem byte sizes for the two NT variants
#define SMEM_NT3 ((8 * SLAB) * 4 + 512)
#define SMEM_NT1 ((4 * SLAB) * 4 + 512)

// ======================= causal flash attention (SIMT fp32, proven) =======================
__global__ void k_attn() {
    extern __shared__ float sm[];
    float* Qs = sm;
    float* KP = sm + 4096;
    float* Vs = sm + 4096 + 4160;
    int qt = blockIdx.x, n = blockIdx.y, b = blockIdx.z;
    int tx = threadIdx.x, ty = threadIdx.y, tid = ty * 16 + tx;
    int q0 = qt * 64;
    const float SCALE = 0.125f;
    {
        int r = tid >> 4, d4 = (tid & 15) * 4;
        for (int rr = r; rr < 64; rr += 16) {
            float4 v = *(const float4*)(g_qkv + ((size_t)(q0 + rr) * B_ + b) * H3_ + n * 192 + d4);
            float* dst = Qs + rr * 64 + d4;
            dst[0] = v.x * SCALE; dst[1] = v.y * SCALE; dst[2] = v.z * SCALE; dst[3] = v.w * SCALE;
        }
    }
    float o[4][4] = {};
    float m_run[4] = {-1e30f, -1e30f, -1e30f, -1e30f};
    float l_run[4] = {0.f, 0.f, 0.f, 0.f};

    for (int j = 0; j <= qt; ++j) {
        __syncthreads();
        int k0 = j * 64;
        {
            int r = tid >> 4, d4 = (tid & 15) * 4;
            for (int rr = r; rr < 64; rr += 16) {
                const float* base = g_qkv + ((size_t)(k0 + rr) * B_ + b) * H3_ + n * 192;
                float4 kv = *(const float4*)(base + 64 + d4);
                KP[rr * 65 + d4 + 0] = kv.x; KP[rr * 65 + d4 + 1] = kv.y;
                KP[rr * 65 + d4 + 2] = kv.z; KP[rr * 65 + d4 + 3] = kv.w;
                float4 vv = *(const float4*)(base + 128 + d4);
                *(float4*)(Vs + rr * 64 + d4) = vv;
            }
        }
        __syncthreads();
        float sacc[4][4] = {};
#pragma unroll 8
        for (int d = 0; d < 64; ++d) {
            float a[4], kr[4];
#pragma unroll
            for (int i = 0; i < 4; i++) a[i]  = Qs[(ty * 4 + i) * 64 + d];
#pragma unroll
            for (int c = 0; c < 4; c++) kr[c] = KP[(tx * 4 + c) * 65 + d];
#pragma unroll
            for (int i = 0; i < 4; i++)
#pragma unroll
                for (int c = 0; c < 4; c++) sacc[i][c] = fmaf(a[i], kr[c], sacc[i][c]);
        }
        if (j == qt) {
#pragma unroll
            for (int i = 0; i < 4; i++)
#pragma unroll
                for (int c = 0; c < 4; c++)
                    if (tx * 4 + c > ty * 4 + i) sacc[i][c] = -1e30f;
        }
        float mx[4], mnew[4], scl[4], rs[4];
#pragma unroll
        for (int i = 0; i < 4; i++) {
            mx[i] = fmaxf(fmaxf(sacc[i][0], sacc[i][1]), fmaxf(sacc[i][2], sacc[i][3]));
            for (int oo = 8; oo; oo >>= 1)
                mx[i] = fmaxf(mx[i], __shfl_xor_sync(0xffffffffu, mx[i], oo));
            mnew[i] = fmaxf(m_run[i], mx[i]);
            scl[i]  = expf(m_run[i] - mnew[i]);
            m_run[i] = mnew[i];
            rs[i] = 0.f;
#pragma unroll
            for (int c = 0; c < 4; c++) {
                sacc[i][c] = expf(sacc[i][c] - mnew[i]);
                rs[i] += sacc[i][c];
            }
            for (int oo = 8; oo; oo >>= 1)
                rs[i] += __shfl_xor_sync(0xffffffffu, rs[i], oo);
            l_run[i] = l_run[i] * scl[i] + rs[i];
#pragma unroll
            for (int c = 0; c < 4; c++) o[i][c] *= scl[i];
        }
        __syncthreads();
#pragma unroll
        for (int i = 0; i < 4; i++)
#pragma unroll
            for (int c = 0; c < 4; c++)
                KP[(ty * 4 + i) * 65 + tx * 4 + c] = sacc[i][c];
        __syncthreads();
#pragma unroll 8
        for (int d = 0; d < 64; ++d) {
            float pi[4], vj[4];
#pragma unroll
            for (int i = 0; i < 4; i++) pi[i] = KP[(ty * 4 + i) * 65 + d];
#pragma unroll
            for (int c = 0; c < 4; c++) vj[c] = Vs[d * 64 + tx * 4 + c];
#pragma unroll
            for (int i = 0; i < 4; i++)
#pragma unroll
                for (int c = 0; c < 4; c++) o[i][c] = fmaf(pi[i], vj[c], o[i][c]);
        }
    }
#pragma unroll
    for (int i = 0; i < 4; i++) {
        float invl = 1.0f / l_run[i];
#pragma unroll
        for (int c = 0; c < 4; c++)
            g_ctx[((size_t)(q0 + ty * 4 + i) * B_ + b) * H_ + n * HD_ + tx * 4 + c] = o[i][c] * invl;
    }
}

// ======================= gate + routing =======================
__global__ void k_gate(const float* __restrict__ gw) {
    int gidx = blockIdx.x * blockDim.x + threadIdx.x;
    int t = gidx >> 5, lane = gidx & 31;
    if (t >= T_) return;
    const float* x = g_ln2 + (size_t)t * H_;
    float s0 = 0, s1 = 0, s2 = 0, s3 = 0;
    for (int h = lane; h < H_; h += 32) {
        float xv = x[h];
        s0 = fmaf(xv, gw[h],          s0);
        s1 = fmaf(xv, gw[H_ + h],     s1);
        s2 = fmaf(xv, gw[2 * H_ + h], s2);
        s3 = fmaf(xv, gw[3 * H_ + h], s3);
    }
    for (int o = 16; o; o >>= 1) {
        s0 += __shfl_xor_sync(0xffffffffu, s0, o);
        s1 += __shfl_xor_sync(0xffffffffu, s1, o);
        s2 += __shfl_xor_sync(0xffffffffu, s2, o);
        s3 += __shfl_xor_sync(0xffffffffu, s3, o);
    }
    if (lane == 0) {
        float l[4] = {s0, s1, s2, s3};
        float mx = fmaxf(fmaxf(l[0], l[1]), fmaxf(l[2], l[3]));
        float ex[4], z = 0.f;
        for (int e = 0; e < 4; e++) { ex[e] = expf(l[e] - mx); z += ex[e]; }
        int best = 0; float bp = ex[0];
        for (int e = 1; e < 4; e++) if (ex[e] > bp) { bp = ex[e]; best = e; }
        g_eidx[t] = best;
        g_prob[t] = bp / z;
    }
}
__global__ void k_zero()  { if (threadIdx.x < E_) g_cnt[threadIdx.x] = 0; }
__global__ void k_count() { int t = blockIdx.x * 256 + threadIdx.x; if (t < T_) atomicAdd(&g_cnt[g_eidx[t]], 1); }
__global__ void k_offsets() {
    if (threadIdx.x == 0) {
        int a = 0;
        for (int e = 0; e < E_; e++) { g_off[e] = a; g_fill[e] = a; a += g_cnt[e]; }
        g_off[E_] = a;
    }
}
__global__ void k_scatter() {
    int t = blockIdx.x * 256 + threadIdx.x;
    if (t < T_) { int p = atomicAdd(&g_fill[g_eidx[t]], 1); g_perm[p] = t; }
}

// ======================= launch =======================
extern "C" void kernel_launch(void* const* d_in, const int* in_sizes, int n_in,
                              void* d_out, int out_size) {
    const float* hidden = (const float*)d_in[0];
    const float* ln1w = (const float*)d_in[2];
    const float* ln1b = (const float*)d_in[3];
    const float* qkvw = (const float*)d_in[4];
    const float* qkvb = (const float*)d_in[5];
    const float* dw   = (const float*)d_in[6];
    const float* db   = (const float*)d_in[7];
    const float* ln2w = (const float*)d_in[8];
    const float* ln2b = (const float*)d_in[9];
    const float* gw   = (const float*)d_in[10];
    const float* w1   = (const float*)d_in[11];
    const float* b1   = (const float*)d_in[12];
    const float* w2   = (const float*)d_in[13];
    const float* b2   = (const float*)d_in[14];
    float* out = (float*)d_out;

    cudaFuncSetAttribute(k_attn, cudaFuncAttributeMaxDynamicSharedMemorySize, 49408);
    cudaFuncSetAttribute((const void*)k_tgemm<0, 768, 1, 3>,
                         cudaFuncAttributeMaxDynamicSharedMemorySize, SMEM_NT3);
    cudaFuncSetAttribute((const void*)k_tgemm<1, 768, 1, 3>,
                         cudaFuncAttributeMaxDynamicSharedMemorySize, SMEM_NT3);
    cudaFuncSetAttribute((const void*)k_tgemm<2, 768, FF_, 1>,
                         cudaFuncAttributeMaxDynamicSharedMemorySize, SMEM_NT1);
    cudaFuncSetAttribute((const void*)k_tgemm<3, 3072, H_, 1>,
                         cudaFuncAttributeMaxDynamicSharedMemorySize, SMEM_NT1);

    k_ln1<<<T_, 256>>>(hidden, ln1w, ln1b);
    k_tgemm<0, 768, 1, 3><<<dim3(H3_ / 128, T_ / 128), 256, SMEM_NT3>>>(qkvw, qkvb, nullptr, nullptr);
    k_attn<<<dim3(S_ / 64, NH_, B_), dim3(16, 16), 49408>>>();
    k_tgemm<1, 768, 1, 3><<<dim3(H_ / 128, T_ / 128), 256, SMEM_NT3>>>(dw, db, hidden, nullptr);
    k_ln2<<<T_, 256>>>(ln2w, ln2b);
    k_gate<<<T_ / 4, 128>>>(gw);
    k_zero<<<1, 32>>>();
    k_count<<<T_ / 256, 256>>>();
    k_offsets<<<1, 32>>>();
    k_scatter<<<T_ / 256, 256>>>();
    k_tgemm<2, 768, FF_, 1><<<dim3(FF_ / 128, T_ / 128, E_), 256, SMEM_NT1>>>(w1, b1, nullptr, nullptr);
    k_tgemm<3, 3072, H_, 1><<<dim3(H_ / 128, T_ / 128, E_), 256, SMEM_NT1>>>(w2, b2, nullptr, out);
}